// round 8
// baseline (speedup 1.0000x reference)
#include <cuda_runtime.h>
#include <cuda_bf16.h>
#include <math.h>
#include <stdint.h>

// ---------------- problem dims ----------------
#define BB   32
#define CC   8
#define TT   20000
#define PP   25
#define LL   800        // TT/PP
#define CP   200        // CC*PP
#define DD   512
#define HH   8
#define DHH  64
#define MM   256
#define NLAYER 2
#define FFND 1024
#define NC   10
#define HID  128
#define ROWS (BB*LL)    // 25600

// ---------------- scratch arena ----------------
#define SZ_H    (ROWS*DD)
#define SZ_BIG  (3*ROWS*DD)
#define SZ_PHI  (BB*HH*LL*MM)
#define OFF_H    0
#define OFF_A    (OFF_H   + SZ_H)
#define OFF_BIG  (OFF_A   + SZ_H)
#define OFF_QF   (OFF_BIG + SZ_BIG)
#define OFF_KF   (OFF_QF  + SZ_PHI)
#define OFF_ATT  (OFF_KF  + SZ_PHI)
#define OFF_KV   (OFF_ATT + SZ_H)
#define OFF_KSUM (OFF_KV  + BB*HH*MM*DHH)
#define OFF_SCR  (OFF_KSUM+ BB*HH*MM)
#define OFF_ALP  (OFF_SCR + ROWS)
#define OFF_FEAT (OFF_ALP + ROWS)
#define ARENA_SZ (OFF_FEAT + BB*2*DD)

__device__ float g_arena[ARENA_SZ];

// ---------------- patchify ----------------
__global__ void patchify_kernel(const float* __restrict__ x, float* __restrict__ tok) {
    int bl = blockIdx.x;
    int b = bl / LL, l = bl % LL;
    int t = threadIdx.x;              // 200 threads
    int c = t / PP, p = t % PP;
    tok[bl * CP + t] = x[(b * CC + c) * TT + l * PP + p];
}

// ---------------- bf16 helpers ----------------
__device__ __forceinline__ void split_bf(float x, __nv_bfloat16& h, __nv_bfloat16& l) {
    h = __float2bfloat16_rn(x);
    l = __float2bfloat16_rn(x - __bfloat162float(h));
}
__device__ __forceinline__ uint32_t pack_bf2(__nv_bfloat16 a, __nv_bfloat16 b) {
    __nv_bfloat162 t; t.x = a; t.y = b;   // .x = low half = even-k element
    uint32_t r; *(__nv_bfloat162*)&r = t; return r;
}
__device__ __forceinline__ void mma_bf16(float* d, const uint32_t* a, const uint32_t* b) {
    asm volatile(
        "mma.sync.aligned.m16n8k16.row.col.f32.bf16.bf16.f32 "
        "{%0,%1,%2,%3}, {%4,%5,%6,%7}, {%8,%9}, {%0,%1,%2,%3};"
        : "+f"(d[0]), "+f"(d[1]), "+f"(d[2]), "+f"(d[3])
        : "r"(a[0]), "r"(a[1]), "r"(a[2]), "r"(a[3]), "r"(b[0]), "r"(b[1]));
}

// ---------------- 3x-bf16 tensor-core GEMM, pre-split smem ---------------
// C = act(A@W + bias) [+C].  A:(Mr x K) rm, W:(K x N) rm, C:(Mr x N) rm.
// Tiles: 128x128x32, 256 threads (8 warps as 2m x 4n, warp tile 64x32).
// smem holds hi/lo bf16-pair (u32) components, double-buffered.
// A tile: [128 rows][16 kpairs] u32, stride 20  -> conflict-free frag loads
// B tile: [16 kpairs][128 cols] u32, stride 136 -> conflict-free frag loads
#define Bb_K 32
#define AS 20
#define BS 136
#define A_TILE (128 * AS)              // 2560 u32
#define B_TILE (16 * BS)               // 2176 u32
#define SMEM_U32 (4 * A_TILE + 4 * B_TILE)   // 18944 u32 = 75776 B
#define GEMM_SMEM (SMEM_U32 * 4)

template<int ACT, bool RESID>
__global__ void __launch_bounds__(256)
gemm_bf16_kernel(const float* __restrict__ A, const float* __restrict__ W,
                 const float* __restrict__ bias, float* __restrict__ C,
                 int Mr, int N, int K)
{
    extern __shared__ uint32_t sm[];
    uint32_t* AHp = sm;
    uint32_t* ALp = sm + 2 * A_TILE;
    uint32_t* BHp = sm + 4 * A_TILE;
    uint32_t* BLp = sm + 4 * A_TILE + 2 * B_TILE;

    int tid = threadIdx.x;
    int lane = tid & 31, wid = tid >> 5;
    int wm = wid & 1, wn = wid >> 1;          // warp tile: m = wm*64, n = wn*32
    int m0 = blockIdx.y * 128, n0 = blockIdx.x * 128;

    float acc[4][4][4];
#pragma unroll
    for (int i = 0; i < 4; i++)
#pragma unroll
        for (int j = 0; j < 4; j++)
#pragma unroll
            for (int r = 0; r < 4; r++) acc[i][j][r] = 0.f;

    uint32_t aH[8], aL[8], bH[8], bL[8];
    int nK = (K + Bb_K - 1) / Bb_K;

    // -------- load + split (gmem -> regs as packed bf16 pairs) --------
    auto load_tiles = [&](int k0) {
#pragma unroll
        for (int r = 0; r < 8; r++) {
            int idx = tid + r * 256;            // 0..2047
            int row = idx >> 4, pair = idx & 15;
            int gk = k0 + 2 * pair;
            const float* p = A + (long)(m0 + row) * K + gk;
            float e0 = (gk     < K) ? p[0] : 0.f;
            float e1 = (gk + 1 < K) ? p[1] : 0.f;
            __nv_bfloat16 h0, l0, h1, l1;
            split_bf(e0, h0, l0); split_bf(e1, h1, l1);
            aH[r] = pack_bf2(h0, h1); aL[r] = pack_bf2(l0, l1);
        }
#pragma unroll
        for (int r = 0; r < 8; r++) {
            int idx = tid + r * 256;
            int pair = idx >> 7, n = idx & 127;
            int gk = k0 + 2 * pair;
            float e0 = (gk     < K) ? W[(long)gk * N + n0 + n]       : 0.f;
            float e1 = (gk + 1 < K) ? W[(long)(gk + 1) * N + n0 + n] : 0.f;
            __nv_bfloat16 h0, l0, h1, l1;
            split_bf(e0, h0, l0); split_bf(e1, h1, l1);
            bH[r] = pack_bf2(h0, h1); bL[r] = pack_bf2(l0, l1);
        }
    };
    auto store_tiles = [&](int buf) {
        uint32_t* AH = AHp + buf * A_TILE;
        uint32_t* AL = ALp + buf * A_TILE;
        uint32_t* BH = BHp + buf * B_TILE;
        uint32_t* BL = BLp + buf * B_TILE;
#pragma unroll
        for (int r = 0; r < 8; r++) {
            int idx = tid + r * 256;
            int row = idx >> 4, pair = idx & 15;
            AH[row * AS + pair] = aH[r];
            AL[row * AS + pair] = aL[r];
        }
#pragma unroll
        for (int r = 0; r < 8; r++) {
            int idx = tid + r * 256;
            int pair = idx >> 7, n = idx & 127;
            BH[pair * BS + n] = bH[r];
            BL[pair * BS + n] = bL[r];
        }
    };

    load_tiles(0);
    store_tiles(0);
    __syncthreads();

    for (int kt = 0; kt < nK; kt++) {
        int buf = kt & 1;
        if (kt + 1 < nK) load_tiles((kt + 1) * Bb_K);

        const uint32_t* AH = AHp + buf * A_TILE;
        const uint32_t* AL = ALp + buf * A_TILE;
        const uint32_t* BH = BHp + buf * B_TILE;
        const uint32_t* BL = BLp + buf * B_TILE;

        // -------- compute: 2 k16 steps, pure LDS + MMA --------
#pragma unroll
        for (int ks = 0; ks < 2; ks++) {
            int pb = ks * 8;                   // kpair base for this k16 step
            uint32_t ahi[4][4], alo[4][4];
#pragma unroll
            for (int mt = 0; mt < 4; mt++) {
                int mrow = wm * 64 + mt * 16 + (lane >> 2);
                int p = pb + (lane & 3);
                ahi[mt][0] = AH[mrow * AS + p];
                ahi[mt][1] = AH[(mrow + 8) * AS + p];
                ahi[mt][2] = AH[mrow * AS + p + 4];
                ahi[mt][3] = AH[(mrow + 8) * AS + p + 4];
                alo[mt][0] = AL[mrow * AS + p];
                alo[mt][1] = AL[(mrow + 8) * AS + p];
                alo[mt][2] = AL[mrow * AS + p + 4];
                alo[mt][3] = AL[(mrow + 8) * AS + p + 4];
            }
            uint32_t bhi[4][2], blo[4][2];
#pragma unroll
            for (int nt = 0; nt < 4; nt++) {
                int ncol = wn * 32 + nt * 8 + (lane >> 2);
                int p = pb + (lane & 3);
                bhi[nt][0] = BH[p * BS + ncol];
                bhi[nt][1] = BH[(p + 4) * BS + ncol];
                blo[nt][0] = BL[p * BS + ncol];
                blo[nt][1] = BL[(p + 4) * BS + ncol];
            }
#pragma unroll
            for (int mt = 0; mt < 4; mt++)
#pragma unroll
                for (int nt = 0; nt < 4; nt++) {
                    mma_bf16(acc[mt][nt], ahi[mt], bhi[nt]);
                    mma_bf16(acc[mt][nt], alo[mt], bhi[nt]);
                    mma_bf16(acc[mt][nt], ahi[mt], blo[nt]);
                }
        }

        if (kt + 1 < nK) {
            store_tiles(buf ^ 1);
            __syncthreads();
        }
    }

    // -------- epilogue --------
#pragma unroll
    for (int mt = 0; mt < 4; mt++) {
#pragma unroll
        for (int nt = 0; nt < 4; nt++) {
            int row = m0 + wm * 64 + mt * 16 + (lane >> 2);
            int col = n0 + wn * 32 + nt * 8 + (lane & 3) * 2;
#pragma unroll
            for (int r = 0; r < 4; r++) {
                int rr = row + (r >> 1) * 8;
                int cc = col + (r & 1);
                float v = acc[mt][nt][r];
                if (bias) v += bias[cc];
                if (ACT == 1) v = 0.5f * v * (1.0f + erff(v * 0.70710678118654752f));
                if (ACT == 2) v = tanhf(v);
                float* cp = &C[(long)rr * N + cc];
                if (RESID) v += *cp;
                *cp = v;
            }
        }
    }
}

// ---------------- LayerNorm over D=512 -------------------------------
__global__ void ln_kernel(const float* __restrict__ X, const float* __restrict__ g,
                          const float* __restrict__ bta, float* __restrict__ Y)
{
    long row = blockIdx.x;
    int tid = threadIdx.x;  // 256
    __shared__ float sh[8];
    float v0 = X[row * DD + tid];
    float v1 = X[row * DD + tid + 256];
    float s = v0 + v1;
#pragma unroll
    for (int o = 16; o > 0; o >>= 1) s += __shfl_xor_sync(0xffffffffu, s, o);
    if ((tid & 31) == 0) sh[tid >> 5] = s;
    __syncthreads();
    if (tid == 0) { float t = 0; for (int i = 0; i < 8; i++) t += sh[i]; sh[0] = t; }
    __syncthreads();
    float mu = sh[0] * (1.0f / DD);
    __syncthreads();
    float d0 = v0 - mu, d1 = v1 - mu;
    s = d0 * d0 + d1 * d1;
#pragma unroll
    for (int o = 16; o > 0; o >>= 1) s += __shfl_xor_sync(0xffffffffu, s, o);
    if ((tid & 31) == 0) sh[tid >> 5] = s;
    __syncthreads();
    if (tid == 0) { float t = 0; for (int i = 0; i < 8; i++) t += sh[i]; sh[0] = t; }
    __syncthreads();
    float var = sh[0] * (1.0f / DD);
    float rstd = rsqrtf(var + 1e-5f);
    Y[row * DD + tid]       = d0 * rstd * g[tid]       + bta[tid];
    Y[row * DD + tid + 256] = d1 * rstd * g[tid + 256] + bta[tid + 256];
}

// ---------------- FAVOR+ phi: Q and K in one launch -------------------
__global__ void phi_kernel(const float* __restrict__ Q, const float* __restrict__ K,
                           const float* __restrict__ omega,
                           float* __restrict__ QPhi, float* __restrict__ KPhi)
{
    int bl = blockIdx.x;
    const float* X = (bl < ROWS) ? Q : K;
    float* Phi = (bl < ROWS) ? QPhi : KPhi;
    if (bl >= ROWS) bl -= ROWS;
    __shared__ float xs[DD];
    int tid = threadIdx.x;  // 256
    const float inv4 = 0.35355339059327379f;  // 1/64^0.25
    xs[tid]       = X[(long)bl * DD + tid]       * inv4;
    xs[tid + 256] = X[(long)bl * DD + tid + 256] * inv4;
    __syncthreads();
    int h = tid >> 5, lane = tid & 31;
    const float* xh = &xs[h * DHH];
    float nsq = 0.f;
#pragma unroll
    for (int d = 0; d < DHH; d++) nsq += xh[d] * xh[d];
    nsq *= 0.5f;
    float acc[8];
#pragma unroll
    for (int j = 0; j < 8; j++) acc[j] = 0.f;
    for (int d = 0; d < DHH; d++) {
        float xv = xh[d];
        const float* om = omega + d * MM + lane;
#pragma unroll
        for (int j = 0; j < 8; j++) acc[j] += xv * om[j * 32];
    }
    int b = bl / LL, l = bl % LL;
    float* outp = Phi + ((long)(b * HH + h) * LL + l) * MM + lane;
#pragma unroll
    for (int j = 0; j < 8; j++) outp[j * 32] = expf(acc[j] - nsq) * 0.0625f;
}

// ---------------- Ksum ----------------------------
__global__ void ksum_kernel(const float* __restrict__ Kf, float* __restrict__ Ksum) {
    int bh = blockIdx.x;
    int m = threadIdx.x;   // 256
    const float* p = Kf + (long)bh * LL * MM + m;
    float s = 0.f;
    for (int l = 0; l < LL; l++) s += p[l * MM];
    Ksum[bh * MM + m] = s;
}

// ---------------- KV[b,h,m,d] = sum_l Kf[l,m] V[l,d] ----------------
__global__ void __launch_bounds__(256)
kv_kernel(const float* __restrict__ Kf, const float* __restrict__ V,
          float* __restrict__ KV)
{
    int bh = blockIdx.x >> 1, mh = blockIdx.x & 1;
    int b = bh / HH, h = bh % HH;
    __shared__ float Ks[32][128];
    __shared__ float Vs[32][64];
    int tid = threadIdx.x;
    int tm = tid >> 3, td = tid & 7;
    float acc[4][8];
#pragma unroll
    for (int i = 0; i < 4; i++)
#pragma unroll
        for (int j = 0; j < 8; j++) acc[i][j] = 0.f;

    for (int l0 = 0; l0 < LL; l0 += 32) {
#pragma unroll
        for (int r = 0; r < 4; r++) {
            int idx = tid * 4 + r * 1024;
            int lr = idx >> 7, mc = idx & 127;
            *(float4*)&Ks[lr][mc] =
                *(const float4*)&Kf[((long)bh * LL + l0 + lr) * MM + mh * 128 + mc];
        }
#pragma unroll
        for (int r = 0; r < 2; r++) {
            int idx = tid * 4 + r * 1024;
            int lr = idx >> 6, dc = idx & 63;
            *(float4*)&Vs[lr][dc] =
                *(const float4*)&V[((long)b * LL + l0 + lr) * DD + h * 64 + dc];
        }
        __syncthreads();
#pragma unroll 4
        for (int l = 0; l < 32; l++) {
            float km[4];
#pragma unroll
            for (int i = 0; i < 4; i++) km[i] = Ks[l][tm * 4 + i];
            float4 v0 = *(float4*)&Vs[l][td * 8];
            float4 v1 = *(float4*)&Vs[l][td * 8 + 4];
            float vr[8] = {v0.x, v0.y, v0.z, v0.w, v1.x, v1.y, v1.z, v1.w};
#pragma unroll
            for (int i = 0; i < 4; i++)
#pragma unroll
                for (int j = 0; j < 8; j++) acc[i][j] += km[i] * vr[j];
        }
        __syncthreads();
    }
#pragma unroll
    for (int i = 0; i < 4; i++) {
        int m = mh * 128 + tm * 4 + i;
#pragma unroll
        for (int j = 0; j < 8; j++)
            KV[((long)bh * MM + m) * DHH + td * 8 + j] = acc[i][j];
    }
}

// ---------------- out = (Qf @ KV) / max(Qf@Ksum,1e-6) ----------------
__global__ void __launch_bounds__(256)
attn_out_kernel(const float* __restrict__ Qf, const float* __restrict__ KV,
                const float* __restrict__ Ksum, float* __restrict__ Att)
{
    int bh = blockIdx.x;
    int l0 = blockIdx.y * 32;
    int b = bh / HH, h = bh % HH;
    __shared__ float Qs[32][64];
    __shared__ float KVs[64][64];
    __shared__ float Ks[64];
    int tid = threadIdx.x;
    int lr = tid >> 3, dg = tid & 7;
    float acc[8];
#pragma unroll
    for (int j = 0; j < 8; j++) acc[j] = 0.f;
    float norm = 0.f;

    for (int mc = 0; mc < 4; mc++) {
        int m0 = mc * 64;
#pragma unroll
        for (int r = 0; r < 2; r++) {
            int idx = tid * 4 + r * 1024;
            int qr = idx >> 6, qm = idx & 63;
            *(float4*)&Qs[qr][qm] =
                *(const float4*)&Qf[((long)bh * LL + l0 + qr) * MM + m0 + qm];
        }
#pragma unroll
        for (int r = 0; r < 4; r++) {
            int idx = tid * 4 + r * 1024;
            int kr = idx >> 6, kd = idx & 63;
            *(float4*)&KVs[kr][kd] =
                *(const float4*)&KV[((long)bh * MM + m0 + kr) * DHH + kd];
        }
        if (tid < 64) Ks[tid] = Ksum[bh * MM + m0 + tid];
        __syncthreads();
#pragma unroll 8
        for (int mm = 0; mm < 64; mm++) {
            float qv = Qs[lr][mm];
            norm += qv * Ks[mm];
            float4 v0 = *(float4*)&KVs[mm][dg * 8];
            float4 v1 = *(float4*)&KVs[mm][dg * 8 + 4];
            acc[0] += qv * v0.x; acc[1] += qv * v0.y;
            acc[2] += qv * v0.z; acc[3] += qv * v0.w;
            acc[4] += qv * v1.x; acc[5] += qv * v1.y;
            acc[6] += qv * v1.z; acc[7] += qv * v1.w;
        }
        __syncthreads();
    }
    float inv = 1.0f / fmaxf(norm, 1e-6f);
    int l = l0 + lr;
    float* outp = Att + ((long)b * LL + l) * DD + h * 64 + dg * 8;
#pragma unroll
    for (int j = 0; j < 8; j++) outp[j] = acc[j] * inv;
}

// ---------------- pooling ---------------------------------------------
__global__ void score_kernel(const float* __restrict__ Tt, const float* __restrict__ w2,
                             float* __restrict__ S)
{
    int row = blockIdx.x * 8 + (threadIdx.x >> 5);
    int lane = threadIdx.x & 31;
    const float* t = Tt + (long)row * HID;
    float s = 0.f;
    for (int i = lane; i < HID; i += 32) s += t[i] * w2[i];
#pragma unroll
    for (int o = 16; o > 0; o >>= 1) s += __shfl_xor_sync(0xffffffffu, s, o);
    if (lane == 0) S[row] = s;
}

__global__ void softmax_kernel(const float* __restrict__ S, float* __restrict__ Alpha) {
    int b = blockIdx.x, tid = threadIdx.x;  // 256 threads
    __shared__ float sh[8];
    float mx = -1e30f;
    for (int i = tid; i < LL; i += 256) mx = fmaxf(mx, S[b * LL + i]);
#pragma unroll
    for (int o = 16; o > 0; o >>= 1) mx = fmaxf(mx, __shfl_xor_sync(0xffffffffu, mx, o));
    if ((tid & 31) == 0) sh[tid >> 5] = mx;
    __syncthreads();
    if (tid == 0) { float t = sh[0]; for (int i = 1; i < 8; i++) t = fmaxf(t, sh[i]); sh[0] = t; }
    __syncthreads();
    float m = sh[0];
    __syncthreads();
    float sum = 0.f;
    for (int i = tid; i < LL; i += 256) sum += expf(S[b * LL + i] - m);
#pragma unroll
    for (int o = 16; o > 0; o >>= 1) sum += __shfl_xor_sync(0xffffffffu, sum, o);
    if ((tid & 31) == 0) sh[tid >> 5] = sum;
    __syncthreads();
    if (tid == 0) { float t = 0; for (int i = 0; i < 8; i++) t += sh[i]; sh[0] = t; }
    __syncthreads();
    float inv = 1.0f / sh[0];
    for (int i = tid; i < LL; i += 256) Alpha[b * LL + i] = expf(S[b * LL + i] - m) * inv;
}

__global__ void muvar_kernel(const float* __restrict__ Hx, const float* __restrict__ Alpha,
                             float* __restrict__ Feat)
{
    int b = blockIdx.x, d = threadIdx.x;  // 512 threads
    float mu = 0.f, sq = 0.f;
    for (int l = 0; l < LL; l++) {
        float a = Alpha[b * LL + l];
        float v = Hx[((long)b * LL + l) * DD + d];
        mu += a * v;
        sq += a * v * v;
    }
    Feat[b * 2 * DD + d] = mu;
    Feat[b * 2 * DD + DD + d] = sqrtf(fmaxf(sq - mu * mu, 1e-8f));
}

__global__ void head_kernel(const float* __restrict__ Feat, const float* __restrict__ Wh,
                            const float* __restrict__ bh_, float* __restrict__ Out)
{
    int b = blockIdx.x, tid = threadIdx.x;  // 256 threads
    float p[NC];
#pragma unroll
    for (int n = 0; n < NC; n++) p[n] = 0.f;
    for (int i = tid; i < 2 * DD; i += 256) {
        float f = Feat[b * 2 * DD + i];
        const float* w = Wh + (long)i * NC;
#pragma unroll
        for (int n = 0; n < NC; n++) p[n] += f * w[n];
    }
    __shared__ float red[NC][256];
#pragma unroll
    for (int n = 0; n < NC; n++) red[n][tid] = p[n];
    __syncthreads();
    for (int s = 128; s > 0; s >>= 1) {
        if (tid < s)
#pragma unroll
            for (int n = 0; n < NC; n++) red[n][tid] += red[n][tid + s];
        __syncthreads();
    }
    if (tid < NC) Out[b * NC + tid] = red[tid][0] + bh_[tid];
}

// ---------------- launch --------------------------------------------
extern "C" void kernel_launch(void* const* d_in, const int* in_sizes, int n_in,
                              void* d_out, int out_size)
{
    const float* x        = (const float*)d_in[0];
    const float* patch_W  = (const float*)d_in[1];
    const float* patch_b  = (const float*)d_in[2];
    const float* patch_g  = (const float*)d_in[3];
    const float* patch_be = (const float*)d_in[4];
    const float* ln1_g    = (const float*)d_in[5];
    const float* ln1_b    = (const float*)d_in[6];
    const float* qW       = (const float*)d_in[7];
    const float* kW       = (const float*)d_in[8];
    const float* vW       = (const float*)d_in[9];
    const float* oW       = (const float*)d_in[10];
    const float* ob       = (const float*)d_in[11];
    const float* omega    = (const float*)d_in[12];
    const float* ln2_g    = (const float*)d_in[13];
    const float* ln2_b    = (const float*)d_in[14];
    const float* f1W      = (const float*)d_in[15];
    const float* f1b      = (const float*)d_in[16];
    const float* f2W      = (const float*)d_in[17];
    const float* f2b      = (const float*)d_in[18];
    const float* poolW1   = (const float*)d_in[19];
    const float* poolW2   = (const float*)d_in[20];
    const float* headW    = (const float*)d_in[21];
    const float* headb    = (const float*)d_in[22];
    float* out = (float*)d_out;

    // opt-in to >48KB dynamic smem (idempotent, not stream-ordered)
    cudaFuncSetAttribute(gemm_bf16_kernel<0, false>, cudaFuncAttributeMaxDynamicSharedMemorySize, GEMM_SMEM);
    cudaFuncSetAttribute(gemm_bf16_kernel<0, true >, cudaFuncAttributeMaxDynamicSharedMemorySize, GEMM_SMEM);
    cudaFuncSetAttribute(gemm_bf16_kernel<1, false>, cudaFuncAttributeMaxDynamicSharedMemorySize, GEMM_SMEM);
    cudaFuncSetAttribute(gemm_bf16_kernel<2, false>, cudaFuncAttributeMaxDynamicSharedMemorySize, GEMM_SMEM);

    float* arena;
    cudaGetSymbolAddress((void**)&arena, g_arena);
    float* h    = arena + OFF_H;
    float* a    = arena + OFF_A;
    float* big  = arena + OFF_BIG;
    float* q    = big;
    float* k    = big + SZ_H;
    float* v    = big + 2 * SZ_H;
    float* ffn  = big;
    float* qf   = arena + OFF_QF;
    float* kf   = arena + OFF_KF;
    float* tok  = arena + OFF_ATT;
    float* att  = arena + OFF_ATT;
    float* kv   = arena + OFF_KV;
    float* ksum = arena + OFF_KSUM;
    float* scr  = arena + OFF_SCR;
    float* alp  = arena + OFF_ALP;
    float* feat = arena + OFF_FEAT;

    dim3 g512(DD / 128, ROWS / 128);    // (4, 200)
    dim3 g1024(FFND / 128, ROWS / 128); // (8, 200)
    dim3 g128(HID / 128, ROWS / 128);   // (1, 200)

    // patchify + embed + LN
    patchify_kernel<<<ROWS, CP>>>(x, tok);
    gemm_bf16_kernel<0, false><<<g512, 256, GEMM_SMEM>>>(tok, patch_W, patch_b, a, ROWS, DD, CP);
    ln_kernel<<<ROWS, 256>>>(a, patch_g, patch_be, h);

    for (int l = 0; l < NLAYER; l++) {
        // attention
        ln_kernel<<<ROWS, 256>>>(h, ln1_g + l * DD, ln1_b + l * DD, a);
        gemm_bf16_kernel<0, false><<<g512, 256, GEMM_SMEM>>>(a, qW + (long)l * DD * DD, nullptr, q, ROWS, DD, DD);
        gemm_bf16_kernel<0, false><<<g512, 256, GEMM_SMEM>>>(a, kW + (long)l * DD * DD, nullptr, k, ROWS, DD, DD);
        gemm_bf16_kernel<0, false><<<g512, 256, GEMM_SMEM>>>(a, vW + (long)l * DD * DD, nullptr, v, ROWS, DD, DD);
        phi_kernel<<<2 * ROWS, 256>>>(q, k, omega + (long)l * DHH * MM, qf, kf);
        ksum_kernel<<<BB * HH, MM>>>(kf, ksum);
        kv_kernel<<<BB * HH * 2, 256>>>(kf, v, kv);
        attn_out_kernel<<<dim3(BB * HH, LL / 32), 256>>>(qf, kv, ksum, att);
        gemm_bf16_kernel<0, true><<<g512, 256, GEMM_SMEM>>>(att, oW + (long)l * DD * DD, ob + l * DD, h, ROWS, DD, DD);
        // FFN
        ln_kernel<<<ROWS, 256>>>(h, ln2_g + l * DD, ln2_b + l * DD, a);
        gemm_bf16_kernel<1, false><<<g1024, 256, GEMM_SMEM>>>(a, f1W + (long)l * DD * FFND, f1b + l * FFND, ffn, ROWS, FFND, DD);
        gemm_bf16_kernel<0, true><<<g512, 256, GEMM_SMEM>>>(ffn, f2W + (long)l * FFND * DD, f2b + l * DD, h, ROWS, DD, FFND);
    }

    // attentive statistics pooling + head
    gemm_bf16_kernel<2, false><<<g128, 256, GEMM_SMEM>>>(h, poolW1, nullptr, ffn, ROWS, HID, DD);
    score_kernel<<<ROWS / 8, 256>>>(ffn, poolW2, scr);
    softmax_kernel<<<BB, 256>>>(scr, alp);
    muvar_kernel<<<BB, DD>>>(h, alp, feat);
    head_kernel<<<BB, 256>>>(feat, headW, headb, out);
}

// round 10
// speedup vs baseline: 1.7637x; 1.7637x over previous
#include <cuda_runtime.h>
#include <cuda_bf16.h>
#include <math.h>
#include <stdint.h>

// ---------------- problem dims ----------------
#define BB   32
#define CC   8
#define TT   20000
#define PP   25
#define LL   800        // TT/PP
#define CP   200        // CC*PP
#define DD   512
#define HH   8
#define DHH  64
#define MM   256
#define NLAYER 2
#define FFND 1024
#define NC   10
#define HID  128
#define ROWS (BB*LL)    // 25600

// ---------------- scratch arena ----------------
#define SZ_H    (ROWS*DD)
#define SZ_BIG  (3*ROWS*DD)
#define SZ_PHI  (BB*HH*LL*MM)
#define OFF_H    0
#define OFF_A    (OFF_H   + SZ_H)
#define OFF_BIG  (OFF_A   + SZ_H)
#define OFF_QF   (OFF_BIG + SZ_BIG)
#define OFF_KF   (OFF_QF  + SZ_PHI)
#define OFF_ATT  (OFF_KF  + SZ_PHI)
#define OFF_KV   (OFF_ATT + SZ_H)
#define OFF_KSUM (OFF_KV  + BB*HH*MM*DHH)
#define OFF_SCR  (OFF_KSUM+ BB*HH*MM)
#define OFF_ALP  (OFF_SCR + ROWS)
#define OFF_FEAT (OFF_ALP + ROWS)
#define OFF_PART (OFF_FEAT + BB*2*DD)
#define ARENA_SZ (OFF_PART + BB*8*2*DD)

__device__ float g_arena[ARENA_SZ];

// ---------------- patchify ----------------
__global__ void patchify_kernel(const float* __restrict__ x, float* __restrict__ tok) {
    int bl = blockIdx.x;
    int b = bl / LL, l = bl % LL;
    int t = threadIdx.x;              // 200 threads
    int c = t / PP, p = t % PP;
    tok[bl * CP + t] = x[(b * CC + c) * TT + l * PP + p];
}

// ---------------- bf16 helpers ----------------
__device__ __forceinline__ void split_bf(float x, __nv_bfloat16& h, __nv_bfloat16& l) {
    h = __float2bfloat16_rn(x);
    l = __float2bfloat16_rn(x - __bfloat162float(h));
}
__device__ __forceinline__ uint32_t pack_bf2(__nv_bfloat16 a, __nv_bfloat16 b) {
    __nv_bfloat162 t; t.x = a; t.y = b;   // .x = low half = even-k element
    uint32_t r; *(__nv_bfloat162*)&r = t; return r;
}
__device__ __forceinline__ void mma_bf16(float* d, const uint32_t* a, const uint32_t* b) {
    asm volatile(
        "mma.sync.aligned.m16n8k16.row.col.f32.bf16.bf16.f32 "
        "{%0,%1,%2,%3}, {%4,%5,%6,%7}, {%8,%9}, {%0,%1,%2,%3};"
        : "+f"(d[0]), "+f"(d[1]), "+f"(d[2]), "+f"(d[3])
        : "r"(a[0]), "r"(a[1]), "r"(a[2]), "r"(a[3]), "r"(b[0]), "r"(b[1]));
}

// ---------------- 3x-bf16 tensor-core GEMM, pre-split smem ---------------
// (byte-identical math to the R8 passing kernel)
#define Bb_K 32
#define AS 20
#define BS 136
#define A_TILE (128 * AS)              // 2560 u32
#define B_TILE (16 * BS)               // 2176 u32
#define SMEM_U32 (4 * A_TILE + 4 * B_TILE)   // 18944 u32 = 75776 B
#define GEMM_SMEM (SMEM_U32 * 4)

template<int ACT, bool RESID>
__global__ void __launch_bounds__(256)
gemm_bf16_kernel(const float* __restrict__ A, const float* __restrict__ W,
                 const float* __restrict__ bias, float* __restrict__ C,
                 int Mr, int N, int K)
{
    extern __shared__ uint32_t sm[];
    uint32_t* AHp = sm;
    uint32_t* ALp = sm + 2 * A_TILE;
    uint32_t* BHp = sm + 4 * A_TILE;
    uint32_t* BLp = sm + 4 * A_TILE + 2 * B_TILE;

    int tid = threadIdx.x;
    int lane = tid & 31, wid = tid >> 5;
    int wm = wid & 1, wn = wid >> 1;          // warp tile: m = wm*64, n = wn*32
    int m0 = blockIdx.y * 128, n0 = blockIdx.x * 128;

    float acc[4][4][4];
#pragma unroll
    for (int i = 0; i < 4; i++)
#pragma unroll
        for (int j = 0; j < 4; j++)
#pragma unroll
            for (int r = 0; r < 4; r++) acc[i][j][r] = 0.f;

    uint32_t aH[8], aL[8], bH[8], bL[8];
    int nK = (K + Bb_K - 1) / Bb_K;

    auto load_tiles = [&](int k0) {
#pragma unroll
        for (int r = 0; r < 8; r++) {
            int idx = tid + r * 256;            // 0..2047
            int row = idx >> 4, pair = idx & 15;
            int gk = k0 + 2 * pair;
            const float* p = A + (long)(m0 + row) * K + gk;
            float e0 = (gk     < K) ? p[0] : 0.f;
            float e1 = (gk + 1 < K) ? p[1] : 0.f;
            __nv_bfloat16 h0, l0, h1, l1;
            split_bf(e0, h0, l0); split_bf(e1, h1, l1);
            aH[r] = pack_bf2(h0, h1); aL[r] = pack_bf2(l0, l1);
        }
#pragma unroll
        for (int r = 0; r < 8; r++) {
            int idx = tid + r * 256;
            int pair = idx >> 7, n = idx & 127;
            int gk = k0 + 2 * pair;
            float e0 = (gk     < K) ? W[(long)gk * N + n0 + n]       : 0.f;
            float e1 = (gk + 1 < K) ? W[(long)(gk + 1) * N + n0 + n] : 0.f;
            __nv_bfloat16 h0, l0, h1, l1;
            split_bf(e0, h0, l0); split_bf(e1, h1, l1);
            bH[r] = pack_bf2(h0, h1); bL[r] = pack_bf2(l0, l1);
        }
    };
    auto store_tiles = [&](int buf) {
        uint32_t* AH = AHp + buf * A_TILE;
        uint32_t* AL = ALp + buf * A_TILE;
        uint32_t* BH = BHp + buf * B_TILE;
        uint32_t* BL = BLp + buf * B_TILE;
#pragma unroll
        for (int r = 0; r < 8; r++) {
            int idx = tid + r * 256;
            int row = idx >> 4, pair = idx & 15;
            AH[row * AS + pair] = aH[r];
            AL[row * AS + pair] = aL[r];
        }
#pragma unroll
        for (int r = 0; r < 8; r++) {
            int idx = tid + r * 256;
            int pair = idx >> 7, n = idx & 127;
            BH[pair * BS + n] = bH[r];
            BL[pair * BS + n] = bL[r];
        }
    };

    load_tiles(0);
    store_tiles(0);
    __syncthreads();

    for (int kt = 0; kt < nK; kt++) {
        int buf = kt & 1;
        if (kt + 1 < nK) load_tiles((kt + 1) * Bb_K);

        const uint32_t* AH = AHp + buf * A_TILE;
        const uint32_t* AL = ALp + buf * A_TILE;
        const uint32_t* BH = BHp + buf * B_TILE;
        const uint32_t* BL = BLp + buf * B_TILE;

#pragma unroll
        for (int ks = 0; ks < 2; ks++) {
            int pb = ks * 8;
            uint32_t ahi[4][4], alo[4][4];
#pragma unroll
            for (int mt = 0; mt < 4; mt++) {
                int mrow = wm * 64 + mt * 16 + (lane >> 2);
                int p = pb + (lane & 3);
                ahi[mt][0] = AH[mrow * AS + p];
                ahi[mt][1] = AH[(mrow + 8) * AS + p];
                ahi[mt][2] = AH[mrow * AS + p + 4];
                ahi[mt][3] = AH[(mrow + 8) * AS + p + 4];
                alo[mt][0] = AL[mrow * AS + p];
                alo[mt][1] = AL[(mrow + 8) * AS + p];
                alo[mt][2] = AL[mrow * AS + p + 4];
                alo[mt][3] = AL[(mrow + 8) * AS + p + 4];
            }
            uint32_t bhi[4][2], blo[4][2];
#pragma unroll
            for (int nt = 0; nt < 4; nt++) {
                int ncol = wn * 32 + nt * 8 + (lane >> 2);
                int p = pb + (lane & 3);
                bhi[nt][0] = BH[p * BS + ncol];
                bhi[nt][1] = BH[(p + 4) * BS + ncol];
                blo[nt][0] = BL[p * BS + ncol];
                blo[nt][1] = BL[(p + 4) * BS + ncol];
            }
#pragma unroll
            for (int mt = 0; mt < 4; mt++)
#pragma unroll
                for (int nt = 0; nt < 4; nt++) {
                    mma_bf16(acc[mt][nt], ahi[mt], bhi[nt]);
                    mma_bf16(acc[mt][nt], alo[mt], bhi[nt]);
                    mma_bf16(acc[mt][nt], ahi[mt], blo[nt]);
                }
        }

        if (kt + 1 < nK) {
            store_tiles(buf ^ 1);
            __syncthreads();
        }
    }

#pragma unroll
    for (int mt = 0; mt < 4; mt++) {
#pragma unroll
        for (int nt = 0; nt < 4; nt++) {
            int row = m0 + wm * 64 + mt * 16 + (lane >> 2);
            int col = n0 + wn * 32 + nt * 8 + (lane & 3) * 2;
#pragma unroll
            for (int r = 0; r < 4; r++) {
                int rr = row + (r >> 1) * 8;
                int cc = col + (r & 1);
                float v = acc[mt][nt][r];
                if (bias) v += bias[cc];
                if (ACT == 1) v = 0.5f * v * (1.0f + erff(v * 0.70710678118654752f));
                if (ACT == 2) v = tanhf(v);
                float* cp = &C[(long)rr * N + cc];
                if (RESID) v += *cp;
                *cp = v;
            }
        }
    }
}

// ---------------- LayerNorm over D=512 -------------------------------
__global__ void ln_kernel(const float* __restrict__ X, const float* __restrict__ g,
                          const float* __restrict__ bta, float* __restrict__ Y)
{
    long row = blockIdx.x;
    int tid = threadIdx.x;  // 256
    __shared__ float sh[8];
    float v0 = X[row * DD + tid];
    float v1 = X[row * DD + tid + 256];
    float s = v0 + v1;
#pragma unroll
    for (int o = 16; o > 0; o >>= 1) s += __shfl_xor_sync(0xffffffffu, s, o);
    if ((tid & 31) == 0) sh[tid >> 5] = s;
    __syncthreads();
    if (tid == 0) { float t = 0; for (int i = 0; i < 8; i++) t += sh[i]; sh[0] = t; }
    __syncthreads();
    float mu = sh[0] * (1.0f / DD);
    __syncthreads();
    float d0 = v0 - mu, d1 = v1 - mu;
    s = d0 * d0 + d1 * d1;
#pragma unroll
    for (int o = 16; o > 0; o >>= 1) s += __shfl_xor_sync(0xffffffffu, s, o);
    if ((tid & 31) == 0) sh[tid >> 5] = s;
    __syncthreads();
    if (tid == 0) { float t = 0; for (int i = 0; i < 8; i++) t += sh[i]; sh[0] = t; }
    __syncthreads();
    float var = sh[0] * (1.0f / DD);
    float rstd = rsqrtf(var + 1e-5f);
    Y[row * DD + tid]       = d0 * rstd * g[tid]       + bta[tid];
    Y[row * DD + tid + 256] = d1 * rstd * g[tid + 256] + bta[tid + 256];
}

// ---------------- FAVOR+ phi, smem-staged: 8 tokens/block, Q or K by blockIdx.y
#define PHI_SMEM ((16384 + 4096) * 4)   // omega 64KB + xs 16KB = 81920 B
__global__ void __launch_bounds__(256)
phi2_kernel(const float* __restrict__ Q, const float* __restrict__ K,
            const float* __restrict__ omega,
            float* __restrict__ QPhi, float* __restrict__ KPhi)
{
    extern __shared__ float ps[];
    float* om_s = ps;            // [64][256] linear
    float* xs_s = ps + 16384;    // [8][512]
    const float* X = blockIdx.y ? K : Q;
    float* Phi = blockIdx.y ? KPhi : QPhi;
    int bl0 = blockIdx.x * 8;
    int tid = threadIdx.x, lane = tid & 31, h = tid >> 5;
    const float inv4 = 0.35355339059327379f;  // 1/64^0.25

#pragma unroll
    for (int i = 0; i < 16; i++) {
        int idx = tid * 4 + i * 1024;
        *(float4*)&om_s[idx] = *(const float4*)&omega[idx];
    }
#pragma unroll
    for (int i = 0; i < 4; i++) {
        int idx = tid * 4 + i * 1024;
        float4 v = *(const float4*)&X[(long)bl0 * DD + idx];
        v.x *= inv4; v.y *= inv4; v.z *= inv4; v.w *= inv4;
        *(float4*)&xs_s[idx] = v;
    }
    __syncthreads();

    float acc[8][8], nsq[8];
#pragma unroll
    for (int t = 0; t < 8; t++) {
        nsq[t] = 0.f;
#pragma unroll
        for (int j = 0; j < 8; j++) acc[t][j] = 0.f;
    }
    for (int d = 0; d < DHH; d++) {
        float om8[8];
#pragma unroll
        for (int j = 0; j < 8; j++) om8[j] = om_s[d * MM + lane + 32 * j];
#pragma unroll
        for (int t = 0; t < 8; t++) {
            float xv = xs_s[t * DD + h * DHH + d];
            nsq[t] += xv * xv;
#pragma unroll
            for (int j = 0; j < 8; j++) acc[t][j] += xv * om8[j];
        }
    }
    int b = bl0 / LL, l0 = bl0 % LL;
#pragma unroll
    for (int t = 0; t < 8; t++) {
        float ns = 0.5f * nsq[t];
        float* outp = Phi + ((long)(b * HH + h) * LL + l0 + t) * MM + lane;
#pragma unroll
        for (int j = 0; j < 8; j++) outp[j * 32] = expf(acc[t][j] - ns) * 0.0625f;
    }
}

// ---------------- Ksum ----------------------------
__global__ void ksum_kernel(const float* __restrict__ Kf, float* __restrict__ Ksum) {
    int bh = blockIdx.x;
    int m = threadIdx.x;   // 256
    const float* p = Kf + (long)bh * LL * MM + m;
    float s = 0.f;
    for (int l = 0; l < LL; l++) s += p[l * MM];
    Ksum[bh * MM + m] = s;
}

// ---------------- KV[b,h,m,d] = sum_l Kf[l,m] V[l,d] ----------------
__global__ void __launch_bounds__(256)
kv_kernel(const float* __restrict__ Kf, const float* __restrict__ V,
          float* __restrict__ KV)
{
    int bh = blockIdx.x >> 1, mh = blockIdx.x & 1;
    int b = bh / HH, h = bh % HH;
    __shared__ float Ks[32][128];
    __shared__ float Vs[32][64];
    int tid = threadIdx.x;
    int tm = tid >> 3, td = tid & 7;
    float acc[4][8];
#pragma unroll
    for (int i = 0; i < 4; i++)
#pragma unroll
        for (int j = 0; j < 8; j++) acc[i][j] = 0.f;

    for (int l0 = 0; l0 < LL; l0 += 32) {
#pragma unroll
        for (int r = 0; r < 4; r++) {
            int idx = tid * 4 + r * 1024;
            int lr = idx >> 7, mc = idx & 127;
            *(float4*)&Ks[lr][mc] =
                *(const float4*)&Kf[((long)bh * LL + l0 + lr) * MM + mh * 128 + mc];
        }
#pragma unroll
        for (int r = 0; r < 2; r++) {
            int idx = tid * 4 + r * 1024;
            int lr = idx >> 6, dc = idx & 63;
            *(float4*)&Vs[lr][dc] =
                *(const float4*)&V[((long)b * LL + l0 + lr) * DD + h * 64 + dc];
        }
        __syncthreads();
#pragma unroll 4
        for (int l = 0; l < 32; l++) {
            float km[4];
#pragma unroll
            for (int i = 0; i < 4; i++) km[i] = Ks[l][tm * 4 + i];
            float4 v0 = *(float4*)&Vs[l][td * 8];
            float4 v1 = *(float4*)&Vs[l][td * 8 + 4];
            float vr[8] = {v0.x, v0.y, v0.z, v0.w, v1.x, v1.y, v1.z, v1.w};
#pragma unroll
            for (int i = 0; i < 4; i++)
#pragma unroll
                for (int j = 0; j < 8; j++) acc[i][j] += km[i] * vr[j];
        }
        __syncthreads();
    }
#pragma unroll
    for (int i = 0; i < 4; i++) {
        int m = mh * 128 + tm * 4 + i;
#pragma unroll
        for (int j = 0; j < 8; j++)
            KV[((long)bh * MM + m) * DHH + td * 8 + j] = acc[i][j];
    }
}

// ---------------- out = (Qf @ KV) / max(Qf@Ksum,1e-6) ----------------
__global__ void __launch_bounds__(256)
attn_out_kernel(const float* __restrict__ Qf, const float* __restrict__ KV,
                const float* __restrict__ Ksum, float* __restrict__ Att)
{
    int bh = blockIdx.x;
    int l0 = blockIdx.y * 32;
    int b = bh / HH, h = bh % HH;
    __shared__ float Qs[32][64];
    __shared__ float KVs[64][64];
    __shared__ float Ks[64];
    int tid = threadIdx.x;
    int lr = tid >> 3, dg = tid & 7;
    float acc[8];
#pragma unroll
    for (int j = 0; j < 8; j++) acc[j] = 0.f;
    float norm = 0.f;

    for (int mc = 0; mc < 4; mc++) {
        int m0 = mc * 64;
#pragma unroll
        for (int r = 0; r < 2; r++) {
            int idx = tid * 4 + r * 1024;
            int qr = idx >> 6, qm = idx & 63;
            *(float4*)&Qs[qr][qm] =
                *(const float4*)&Qf[((long)bh * LL + l0 + qr) * MM + m0 + qm];
        }
#pragma unroll
        for (int r = 0; r < 4; r++) {
            int idx = tid * 4 + r * 1024;
            int kr = idx >> 6, kd = idx & 63;
            *(float4*)&KVs[kr][kd] =
                *(const float4*)&KV[((long)bh * MM + m0 + kr) * DHH + kd];
        }
        if (tid < 64) Ks[tid] = Ksum[bh * MM + m0 + tid];
        __syncthreads();
#pragma unroll 8
        for (int mm = 0; mm < 64; mm++) {
            float qv = Qs[lr][mm];
            norm += qv * Ks[mm];
            float4 v0 = *(float4*)&KVs[mm][dg * 8];
            float4 v1 = *(float4*)&KVs[mm][dg * 8 + 4];
            acc[0] += qv * v0.x; acc[1] += qv * v0.y;
            acc[2] += qv * v0.z; acc[3] += qv * v0.w;
            acc[4] += qv * v1.x; acc[5] += qv * v1.y;
            acc[6] += qv * v1.z; acc[7] += qv * v1.w;
        }
        __syncthreads();
    }
    float inv = 1.0f / fmaxf(norm, 1e-6f);
    int l = l0 + lr;
    float* outp = Att + ((long)b * LL + l) * DD + h * 64 + dg * 8;
#pragma unroll
    for (int j = 0; j < 8; j++) outp[j] = acc[j] * inv;
}

// ---------------- pooling ---------------------------------------------
__global__ void score_kernel(const float* __restrict__ Tt, const float* __restrict__ w2,
                             float* __restrict__ S)
{
    int row = blockIdx.x * 8 + (threadIdx.x >> 5);
    int lane = threadIdx.x & 31;
    const float* t = Tt + (long)row * HID;
    float s = 0.f;
    for (int i = lane; i < HID; i += 32) s += t[i] * w2[i];
#pragma unroll
    for (int o = 16; o > 0; o >>= 1) s += __shfl_xor_sync(0xffffffffu, s, o);
    if (lane == 0) S[row] = s;
}

__global__ void softmax_kernel(const float* __restrict__ S, float* __restrict__ Alpha) {
    int b = blockIdx.x, tid = threadIdx.x;  // 256 threads
    __shared__ float sh[8];
    float mx = -1e30f;
    for (int i = tid; i < LL; i += 256) mx = fmaxf(mx, S[b * LL + i]);
#pragma unroll
    for (int o = 16; o > 0; o >>= 1) mx = fmaxf(mx, __shfl_xor_sync(0xffffffffu, mx, o));
    if ((tid & 31) == 0) sh[tid >> 5] = mx;
    __syncthreads();
    if (tid == 0) { float t = sh[0]; for (int i = 1; i < 8; i++) t = fmaxf(t, sh[i]); sh[0] = t; }
    __syncthreads();
    float m = sh[0];
    __syncthreads();
    float sum = 0.f;
    for (int i = tid; i < LL; i += 256) sum += expf(S[b * LL + i] - m);
#pragma unroll
    for (int o = 16; o > 0; o >>= 1) sum += __shfl_xor_sync(0xffffffffu, sum, o);
    if ((tid & 31) == 0) sh[tid >> 5] = sum;
    __syncthreads();
    if (tid == 0) { float t = 0; for (int i = 0; i < 8; i++) t += sh[i]; sh[0] = t; }
    __syncthreads();
    float inv = 1.0f / sh[0];
    for (int i = tid; i < LL; i += 256) Alpha[b * LL + i] = expf(S[b * LL + i] - m) * inv;
}

// ---------------- attentive stats pooling: 2-stage -----------------------
__global__ void muvar_part_kernel(const float* __restrict__ Hx, const float* __restrict__ Alpha,
                                  float* __restrict__ Part)
{
    int b = blockIdx.x, c = blockIdx.y, d = threadIdx.x;  // 512 threads
    float mu = 0.f, sq = 0.f;
    int l0 = c * (LL / 8);
    for (int l = l0; l < l0 + LL / 8; l++) {
        float a = Alpha[b * LL + l];
        float v = Hx[((long)b * LL + l) * DD + d];
        mu += a * v;
        sq += a * v * v;
    }
    Part[((long)(b * 8 + c) * 2) * DD + d]     = mu;
    Part[((long)(b * 8 + c) * 2 + 1) * DD + d] = sq;
}

__global__ void muvar_fin_kernel(const float* __restrict__ Part, float* __restrict__ Feat)
{
    int b = blockIdx.x, d = threadIdx.x;  // 512 threads
    float mu = 0.f, sq = 0.f;
#pragma unroll
    for (int c = 0; c < 8; c++) {
        mu += Part[((long)(b * 8 + c) * 2) * DD + d];
        sq += Part[((long)(b * 8 + c) * 2 + 1) * DD + d];
    }
    Feat[b * 2 * DD + d] = mu;
    Feat[b * 2 * DD + DD + d] = sqrtf(fmaxf(sq - mu * mu, 1e-8f));
}

__global__ void head_kernel(const float* __restrict__ Feat, const float* __restrict__ Wh,
                            const float* __restrict__ bh_, float* __restrict__ Out)
{
    int b = blockIdx.x, tid = threadIdx.x;  // 256 threads
    float p[NC];
#pragma unroll
    for (int n = 0; n < NC; n++) p[n] = 0.f;
    for (int i = tid; i < 2 * DD; i += 256) {
        float f = Feat[b * 2 * DD + i];
        const float* w = Wh + (long)i * NC;
#pragma unroll
        for (int n = 0; n < NC; n++) p[n] += f * w[n];
    }
    __shared__ float red[NC][256];
#pragma unroll
    for (int n = 0; n < NC; n++) red[n][tid] = p[n];
    __syncthreads();
    for (int s = 128; s > 0; s >>= 1) {
        if (tid < s)
#pragma unroll
            for (int n = 0; n < NC; n++) red[n][tid] += red[n][tid + s];
        __syncthreads();
    }
    if (tid < NC) Out[b * NC + tid] = red[tid][0] + bh_[tid];
}

// ---------------- launch --------------------------------------------
extern "C" void kernel_launch(void* const* d_in, const int* in_sizes, int n_in,
                              void* d_out, int out_size)
{
    const float* x        = (const float*)d_in[0];
    const float* patch_W  = (const float*)d_in[1];
    const float* patch_b  = (const float*)d_in[2];
    const float* patch_g  = (const float*)d_in[3];
    const float* patch_be = (const float*)d_in[4];
    const float* ln1_g    = (const float*)d_in[5];
    const float* ln1_b    = (const float*)d_in[6];
    const float* qW       = (const float*)d_in[7];
    const float* kW       = (const float*)d_in[8];
    const float* vW       = (const float*)d_in[9];
    const float* oW       = (const float*)d_in[10];
    const float* ob       = (const float*)d_in[11];
    const float* omega    = (const float*)d_in[12];
    const float* ln2_g    = (const float*)d_in[13];
    const float* ln2_b    = (const float*)d_in[14];
    const float* f1W      = (const float*)d_in[15];
    const float* f1b      = (const float*)d_in[16];
    const float* f2W      = (const float*)d_in[17];
    const float* f2b      = (const float*)d_in[18];
    const float* poolW1   = (const float*)d_in[19];
    const float* poolW2   = (const float*)d_in[20];
    const float* headW    = (const float*)d_in[21];
    const float* headb    = (const float*)d_in[22];
    float* out = (float*)d_out;

    // opt-in to >48KB dynamic smem (idempotent, not stream-ordered)
    cudaFuncSetAttribute(gemm_bf16_kernel<0, false>, cudaFuncAttributeMaxDynamicSharedMemorySize, GEMM_SMEM);
    cudaFuncSetAttribute(gemm_bf16_kernel<0, true >, cudaFuncAttributeMaxDynamicSharedMemorySize, GEMM_SMEM);
    cudaFuncSetAttribute(gemm_bf16_kernel<1, false>, cudaFuncAttributeMaxDynamicSharedMemorySize, GEMM_SMEM);
    cudaFuncSetAttribute(gemm_bf16_kernel<2, false>, cudaFuncAttributeMaxDynamicSharedMemorySize, GEMM_SMEM);
    cudaFuncSetAttribute(phi2_kernel, cudaFuncAttributeMaxDynamicSharedMemorySize, PHI_SMEM);

    float* arena;
    cudaGetSymbolAddress((void**)&arena, g_arena);
    float* h    = arena + OFF_H;
    float* a    = arena + OFF_A;
    float* big  = arena + OFF_BIG;
    float* q    = big;
    float* k    = big + SZ_H;
    float* v    = big + 2 * SZ_H;
    float* ffn  = big;
    float* qf   = arena + OFF_QF;
    float* kf   = arena + OFF_KF;
    float* tok  = arena + OFF_ATT;
    float* att  = arena + OFF_ATT;
    float* kv   = arena + OFF_KV;
    float* ksum = arena + OFF_KSUM;
    float* scr  = arena + OFF_SCR;
    float* alp  = arena + OFF_ALP;
    float* feat = arena + OFF_FEAT;
    float* part = arena + OFF_PART;

    dim3 g512(DD / 128, ROWS / 128);    // (4, 200)
    dim3 g1024(FFND / 128, ROWS / 128); // (8, 200)
    dim3 g128(HID / 128, ROWS / 128);   // (1, 200)

    // patchify + embed + LN
    patchify_kernel<<<ROWS, CP>>>(x, tok);
    gemm_bf16_kernel<0, false><<<g512, 256, GEMM_SMEM>>>(tok, patch_W, patch_b, a, ROWS, DD, CP);
    ln_kernel<<<ROWS, 256>>>(a, patch_g, patch_be, h);

    for (int l = 0; l < NLAYER; l++) {
        // attention
        ln_kernel<<<ROWS, 256>>>(h, ln1_g + l * DD, ln1_b + l * DD, a);
        gemm_bf16_kernel<0, false><<<g512, 256, GEMM_SMEM>>>(a, qW + (long)l * DD * DD, nullptr, q, ROWS, DD, DD);
        gemm_bf16_kernel<0, false><<<g512, 256, GEMM_SMEM>>>(a, kW + (long)l * DD * DD, nullptr, k, ROWS, DD, DD);
        gemm_bf16_kernel<0, false><<<g512, 256, GEMM_SMEM>>>(a, vW + (long)l * DD * DD, nullptr, v, ROWS, DD, DD);
        phi2_kernel<<<dim3(ROWS / 8, 2), 256, PHI_SMEM>>>(q, k, omega + (long)l * DHH * MM, qf, kf);
        ksum_kernel<<<BB * HH, MM>>>(kf, ksum);
        kv_kernel<<<BB * HH * 2, 256>>>(kf, v, kv);
        attn_out_kernel<<<dim3(BB * HH, LL / 32), 256>>>(qf, kv, ksum, att);
        gemm_bf16_kernel<0, true><<<g512, 256, GEMM_SMEM>>>(att, oW + (long)l * DD * DD, ob + l * DD, h, ROWS, DD, DD);
        // FFN
        ln_kernel<<<ROWS, 256>>>(h, ln2_g + l * DD, ln2_b + l * DD, a);
        gemm_bf16_kernel<1, false><<<g1024, 256, GEMM_SMEM>>>(a, f1W + (long)l * DD * FFND, f1b + l * FFND, ffn, ROWS, FFND, DD);
        gemm_bf16_kernel<0, true><<<g512, 256, GEMM_SMEM>>>(ffn, f2W + (long)l * FFND * DD, f2b + l * DD, h, ROWS, DD, FFND);
    }

    // attentive statistics pooling + head
    gemm_bf16_kernel<2, false><<<g128, 256, GEMM_SMEM>>>(h, poolW1, nullptr, ffn, ROWS, HID, DD);
    score_kernel<<<ROWS / 8, 256>>>(ffn, poolW2, scr);
    softmax_kernel<<<BB, 256>>>(scr, alp);
    muvar_part_kernel<<<dim3(BB, 8), DD>>>(h, alp, part);
    muvar_fin_kernel<<<BB, DD>>>(part, feat);
    head_kernel<<<BB, 256>>>(feat, headW, headb, out);
}

// round 13
// speedup vs baseline: 2.4516x; 1.3900x over previous
#include <cuda_runtime.h>
#include <cuda_fp16.h>
#include <math.h>
#include <stdint.h>

// ---------------- problem dims ----------------
#define BB   32
#define CC   8
#define TT   20000
#define PP   25
#define LL   800        // TT/PP
#define CP   200        // CC*PP
#define DD   512
#define HH   8
#define DHH  64
#define MM   256
#define NLAYER 2
#define FFND 1024
#define NC   10
#define HID  128
#define ROWS (BB*LL)    // 25600

// ---------------- scratch arena ----------------
#define SZ_H    (ROWS*DD)
#define SZ_BIG  (3*ROWS*DD)
#define SZ_PHI  (BB*HH*LL*MM)
#define OFF_H    0
#define OFF_A    (OFF_H   + SZ_H)
#define OFF_BIG  (OFF_A   + SZ_H)
#define OFF_QF   (OFF_BIG + SZ_BIG)
#define OFF_KF   (OFF_QF  + SZ_PHI)
#define OFF_ATT  (OFF_KF  + SZ_PHI)
#define OFF_KV   (OFF_ATT + SZ_H)
#define OFF_KSUM (OFF_KV  + BB*HH*MM*DHH)
#define OFF_SCR  (OFF_KSUM+ BB*HH*MM)
#define OFF_ALP  (OFF_SCR + ROWS)
#define OFF_FEAT (OFF_ALP + ROWS)
#define OFF_PART (OFF_FEAT + BB*2*DD)
#define ARENA_SZ (OFF_PART + BB*8*2*DD)

__device__ float g_arena[ARENA_SZ];

// ---------------- patchify ----------------
__global__ void patchify_kernel(const float* __restrict__ x, float* __restrict__ tok) {
    int bl = blockIdx.x;
    int b = bl / LL, l = bl % LL;
    int t = threadIdx.x;              // 200 threads
    int c = t / PP, p = t % PP;
    tok[bl * CP + t] = x[(b * CC + c) * TT + l * PP + p];
}

// ---------------- fp16 helpers ----------------
__device__ __forceinline__ uint32_t pack_h2(float e0, float e1) {
    __half2 t = __floats2half2_rn(e0, e1);   // .x = low half = even-k element
    uint32_t r; *(__half2*)&r = t; return r;
}
__device__ __forceinline__ void mma_fp16(float* d, const uint32_t* a, const uint32_t* b) {
    asm volatile(
        "mma.sync.aligned.m16n8k16.row.col.f32.f16.f16.f32 "
        "{%0,%1,%2,%3}, {%4,%5,%6,%7}, {%8,%9}, {%0,%1,%2,%3};"
        : "+f"(d[0]), "+f"(d[1]), "+f"(d[2]), "+f"(d[3])
        : "r"(a[0]), "r"(a[1]), "r"(a[2]), "r"(a[3]), "r"(b[0]), "r"(b[1]));
}

// ---------------- 1-pass fp16 tensor-core GEMM -------------------------
// C = act(A@W + bias) [+C].  A:(Mr x K) rm, W:(K x N) rm, C:(Mr x N) rm.
// Tiles: 128x128x32, 256 threads (8 warps as 2m x 4n, warp tile 64x32).
// smem holds packed half2 (u32) tiles, double-buffered, static smem.
// A tile: [128 rows][16 kpairs] u32, stride 20  -> conflict-free frag loads
// B tile: [16 kpairs][128 cols] u32, stride 136 -> conflict-free frag loads
#define Bb_K 32
#define AS 20
#define BS 136
#define A_TILE (128 * AS)              // 2560 u32
#define B_TILE (16 * BS)               // 2176 u32
#define SMEM_U32 (2 * A_TILE + 2 * B_TILE)   // 9472 u32 = 37888 B

template<int ACT, bool RESID>
__global__ void __launch_bounds__(256)
gemm_fp16_kernel(const float* __restrict__ A, const float* __restrict__ W,
                 const float* __restrict__ bias, float* __restrict__ C,
                 int Mr, int N, int K)
{
    __shared__ uint32_t sm[SMEM_U32];
    uint32_t* AHp = sm;                     // 2 buffers of A_TILE
    uint32_t* BHp = sm + 2 * A_TILE;        // 2 buffers of B_TILE

    int tid = threadIdx.x;
    int lane = tid & 31, wid = tid >> 5;
    int wm = wid & 1, wn = wid >> 1;          // warp tile: m = wm*64, n = wn*32
    int m0 = blockIdx.y * 128, n0 = blockIdx.x * 128;

    float acc[4][4][4];
#pragma unroll
    for (int i = 0; i < 4; i++)
#pragma unroll
        for (int j = 0; j < 4; j++)
#pragma unroll
            for (int r = 0; r < 4; r++) acc[i][j][r] = 0.f;

    uint32_t aH[8], bH[8];
    int nK = (K + Bb_K - 1) / Bb_K;

    // -------- load + convert (gmem -> regs as packed half2) --------
    auto load_tiles = [&](int k0) {
#pragma unroll
        for (int r = 0; r < 8; r++) {
            int idx = tid + r * 256;            // 0..2047
            int row = idx >> 4, pair = idx & 15;
            int gk = k0 + 2 * pair;
            const float* p = A + (long)(m0 + row) * K + gk;
            float e0 = (gk     < K) ? p[0] : 0.f;
            float e1 = (gk + 1 < K) ? p[1] : 0.f;
            aH[r] = pack_h2(e0, e1);
        }
#pragma unroll
        for (int r = 0; r < 8; r++) {
            int idx = tid + r * 256;
            int pair = idx >> 7, n = idx & 127;
            int gk = k0 + 2 * pair;
            float e0 = (gk     < K) ? W[(long)gk * N + n0 + n]       : 0.f;
            float e1 = (gk + 1 < K) ? W[(long)(gk + 1) * N + n0 + n] : 0.f;
            bH[r] = pack_h2(e0, e1);
        }
    };
    auto store_tiles = [&](int buf) {
        uint32_t* AH = AHp + buf * A_TILE;
        uint32_t* BH = BHp + buf * B_TILE;
#pragma unroll
        for (int r = 0; r < 8; r++) {
            int idx = tid + r * 256;
            int row = idx >> 4, pair = idx & 15;
            AH[row * AS + pair] = aH[r];
        }
#pragma unroll
        for (int r = 0; r < 8; r++) {
            int idx = tid + r * 256;
            int pair = idx >> 7, n = idx & 127;
            BH[pair * BS + n] = bH[r];
        }
    };

    load_tiles(0);
    store_tiles(0);
    __syncthreads();

    for (int kt = 0; kt < nK; kt++) {
        int buf = kt & 1;
        if (kt + 1 < nK) load_tiles((kt + 1) * Bb_K);

        const uint32_t* AH = AHp + buf * A_TILE;
        const uint32_t* BH = BHp + buf * B_TILE;

        // -------- compute: 2 k16 steps, pure LDS + MMA --------
#pragma unroll
        for (int ks = 0; ks < 2; ks++) {
            int pb = ks * 8;                   // kpair base for this k16 step
            uint32_t ahi[4][4];
#pragma unroll
            for (int mt = 0; mt < 4; mt++) {
                int mrow = wm * 64 + mt * 16 + (lane >> 2);
                int p = pb + (lane & 3);
                ahi[mt][0] = AH[mrow * AS + p];
                ahi[mt][1] = AH[(mrow + 8) * AS + p];
                ahi[mt][2] = AH[mrow * AS + p + 4];
                ahi[mt][3] = AH[(mrow + 8) * AS + p + 4];
            }
            uint32_t bhi[4][2];
#pragma unroll
            for (int nt = 0; nt < 4; nt++) {
                int ncol = wn * 32 + nt * 8 + (lane >> 2);
                int p = pb + (lane & 3);
                bhi[nt][0] = BH[p * BS + ncol];
                bhi[nt][1] = BH[(p + 4) * BS + ncol];
            }
#pragma unroll
            for (int mt = 0; mt < 4; mt++)
#pragma unroll
                for (int nt = 0; nt < 4; nt++)
                    mma_fp16(acc[mt][nt], ahi[mt], bhi[nt]);
        }

        if (kt + 1 < nK) {
            store_tiles(buf ^ 1);
            __syncthreads();
        }
    }

    // -------- epilogue --------
#pragma unroll
    for (int mt = 0; mt < 4; mt++) {
#pragma unroll
        for (int nt = 0; nt < 4; nt++) {
            int row = m0 + wm * 64 + mt * 16 + (lane >> 2);
            int col = n0 + wn * 32 + nt * 8 + (lane & 3) * 2;
#pragma unroll
            for (int r = 0; r < 4; r++) {
                int rr = row + (r >> 1) * 8;
                int cc = col + (r & 1);
                float v = acc[mt][nt][r];
                if (bias) v += bias[cc];
                if (ACT == 1) v = 0.5f * v * (1.0f + erff(v * 0.70710678118654752f));
                if (ACT == 2) v = tanhf(v);
                float* cp = &C[(long)rr * N + cc];
                if (RESID) v += *cp;
                *cp = v;
            }
        }
    }
}

// ---------------- LayerNorm over D=512 -------------------------------
__global__ void ln_kernel(const float* __restrict__ X, const float* __restrict__ g,
                          const float* __restrict__ bta, float* __restrict__ Y)
{
    long row = blockIdx.x;
    int tid = threadIdx.x;  // 256
    __shared__ float sh[8];
    float v0 = X[row * DD + tid];
    float v1 = X[row * DD + tid + 256];
    float s = v0 + v1;
#pragma unroll
    for (int o = 16; o > 0; o >>= 1) s += __shfl_xor_sync(0xffffffffu, s, o);
    if ((tid & 31) == 0) sh[tid >> 5] = s;
    __syncthreads();
    if (tid == 0) { float t = 0; for (int i = 0; i < 8; i++) t += sh[i]; sh[0] = t; }
    __syncthreads();
    float mu = sh[0] * (1.0f / DD);
    __syncthreads();
    float d0 = v0 - mu, d1 = v1 - mu;
    s = d0 * d0 + d1 * d1;
#pragma unroll
    for (int o = 16; o > 0; o >>= 1) s += __shfl_xor_sync(0xffffffffu, s, o);
    if ((tid & 31) == 0) sh[tid >> 5] = s;
    __syncthreads();
    if (tid == 0) { float t = 0; for (int i = 0; i < 8; i++) t += sh[i]; sh[0] = t; }
    __syncthreads();
    float var = sh[0] * (1.0f / DD);
    float rstd = rsqrtf(var + 1e-5f);
    Y[row * DD + tid]       = d0 * rstd * g[tid]       + bta[tid];
    Y[row * DD + tid + 256] = d1 * rstd * g[tid + 256] + bta[tid + 256];
}

// ---------------- FAVOR+ phi, smem-staged: 8 tokens/block, Q or K by blockIdx.y
#define PHI_SMEM ((16384 + 4096) * 4)   // omega 64KB + xs 16KB = 81920 B
__global__ void __launch_bounds__(256)
phi2_kernel(const float* __restrict__ Q, const float* __restrict__ K,
            const float* __restrict__ omega,
            float* __restrict__ QPhi, float* __restrict__ KPhi)
{
    extern __shared__ float ps[];
    float* om_s = ps;            // [64][256] linear
    float* xs_s = ps + 16384;    // [8][512]
    const float* X = blockIdx.y ? K : Q;
    float* Phi = blockIdx.y ? KPhi : QPhi;
    int bl0 = blockIdx.x * 8;
    int tid = threadIdx.x, lane = tid & 31, h = tid >> 5;
    const float inv4 = 0.35355339059327379f;  // 1/64^0.25

#pragma unroll
    for (int i = 0; i < 16; i++) {
        int idx = tid * 4 + i * 1024;
        *(float4*)&om_s[idx] = *(const float4*)&omega[idx];
    }
#pragma unroll
    for (int i = 0; i < 4; i++) {
        int idx = tid * 4 + i * 1024;
        float4 v = *(const float4*)&X[(long)bl0 * DD + idx];
        v.x *= inv4; v.y *= inv4; v.z *= inv4; v.w *= inv4;
        *(float4*)&xs_s[idx] = v;
    }
    __syncthreads();

    float acc[8][8], nsq[8];
#pragma unroll
    for (int t = 0; t < 8; t++) {
        nsq[t] = 0.f;
#pragma unroll
        for (int j = 0; j < 8; j++) acc[t][j] = 0.f;
    }
    for (int d = 0; d < DHH; d++) {
        float om8[8];
#pragma unroll
        for (int j = 0; j < 8; j++) om8[j] = om_s[d * MM + lane + 32 * j];
#pragma unroll
        for (int t = 0; t < 8; t++) {
            float xv = xs_s[t * DD + h * DHH + d];
            nsq[t] += xv * xv;
#pragma unroll
            for (int j = 0; j < 8; j++) acc[t][j] += xv * om8[j];
        }
    }
    int b = bl0 / LL, l0 = bl0 % LL;
#pragma unroll
    for (int t = 0; t < 8; t++) {
        float ns = 0.5f * nsq[t];
        float* outp = Phi + ((long)(b * HH + h) * LL + l0 + t) * MM + lane;
#pragma unroll
        for (int j = 0; j < 8; j++) outp[j * 32] = expf(acc[t][j] - ns) * 0.0625f;
    }
}

// ---------------- Ksum ----------------------------
__global__ void ksum_kernel(const float* __restrict__ Kf, float* __restrict__ Ksum) {
    int bh = blockIdx.x;
    int m = threadIdx.x;   // 256
    const float* p = Kf + (long)bh * LL * MM + m;
    float s = 0.f;
    for (int l = 0; l < LL; l++) s += p[l * MM];
    Ksum[bh * MM + m] = s;
}

// ---------------- KV[b,h,m,d] = sum_l Kf[l,m] V[l,d] ----------------
__global__ void __launch_bounds__(256)
kv_kernel(const float* __restrict__ Kf, const float* __restrict__ V,
          float* __restrict__ KV)
{
    int bh = blockIdx.x >> 1, mh = blockIdx.x & 1;
    int b = bh / HH, h = bh % HH;
    __shared__ float Ks[32][128];
    __shared__ float Vs[32][64];
    int tid = threadIdx.x;
    int tm = tid >> 3, td = tid & 7;
    float acc[4][8];
#pragma unroll
    for (int i = 0; i < 4; i++)
#pragma unroll
        for (int j = 0; j < 8; j++) acc[i][j] = 0.f;

    for (int l0 = 0; l0 < LL; l0 += 32) {
#pragma unroll
        for (int r = 0; r < 4; r++) {
            int idx = tid * 4 + r * 1024;
            int lr = idx >> 7, mc = idx & 127;
            *(float4*)&Ks[lr][mc] =
                *(const float4*)&Kf[((long)bh * LL + l0 + lr) * MM + mh * 128 + mc];
        }
#pragma unroll
        for (int r = 0; r < 2; r++) {
            int idx = tid * 4 + r * 1024;
            int lr = idx >> 6, dc = idx & 63;
            *(float4*)&Vs[lr][dc] =
                *(const float4*)&V[((long)b * LL + l0 + lr) * DD + h * 64 + dc];
        }
        __syncthreads();
#pragma unroll 4
        for (int l = 0; l < 32; l++) {
            float km[4];
#pragma unroll
            for (int i = 0; i < 4; i++) km[i] = Ks[l][tm * 4 + i];
            float4 v0 = *(float4*)&Vs[l][td * 8];
            float4 v1 = *(float4*)&Vs[l][td * 8 + 4];
            float vr[8] = {v0.x, v0.y, v0.z, v0.w, v1.x, v1.y, v1.z, v1.w};
#pragma unroll
            for (int i = 0; i < 4; i++)
#pragma unroll
                for (int j = 0; j < 8; j++) acc[i][j] += km[i] * vr[j];
        }
        __syncthreads();
    }
#pragma unroll
    for (int i = 0; i < 4; i++) {
        int m = mh * 128 + tm * 4 + i;
#pragma unroll
        for (int j = 0; j < 8; j++)
            KV[((long)bh * MM + m) * DHH + td * 8 + j] = acc[i][j];
    }
}

// ---------------- out = (Qf @ KV) / max(Qf@Ksum,1e-6) ----------------
__global__ void __launch_bounds__(256)
attn_out_kernel(const float* __restrict__ Qf, const float* __restrict__ KV,
                const float* __restrict__ Ksum, float* __restrict__ Att)
{
    int bh = blockIdx.x;
    int l0 = blockIdx.y * 32;
    int b = bh / HH, h = bh % HH;
    __shared__ float Qs[32][64];
    __shared__ float KVs[64][64];
    __shared__ float Ks[64];
    int tid = threadIdx.x;
    int lr = tid >> 3, dg = tid & 7;
    float acc[8];
#pragma unroll
    for (int j = 0; j < 8; j++) acc[j] = 0.f;
    float norm = 0.f;

    for (int mc = 0; mc < 4; mc++) {
        int m0 = mc * 64;
#pragma unroll
        for (int r = 0; r < 2; r++) {
            int idx = tid * 4 + r * 1024;
            int qr = idx >> 6, qm = idx & 63;
            *(float4*)&Qs[qr][qm] =
                *(const float4*)&Qf[((long)bh * LL + l0 + qr) * MM + m0 + qm];
        }
#pragma unroll
        for (int r = 0; r < 4; r++) {
            int idx = tid * 4 + r * 1024;
            int kr = idx >> 6, kd = idx & 63;
            *(float4*)&KVs[kr][kd] =
                *(const float4*)&KV[((long)bh * MM + m0 + kr) * DHH + kd];
        }
        if (tid < 64) Ks[tid] = Ksum[bh * MM + m0 + tid];
        __syncthreads();
#pragma unroll 8
        for (int mm = 0; mm < 64; mm++) {
            float qv = Qs[lr][mm];
            norm += qv * Ks[mm];
            float4 v0 = *(float4*)&KVs[mm][dg * 8];
            float4 v1 = *(float4*)&KVs[mm][dg * 8 + 4];
            acc[0] += qv * v0.x; acc[1] += qv * v0.y;
            acc[2] += qv * v0.z; acc[3] += qv * v0.w;
            acc[4] += qv * v1.x; acc[5] += qv * v1.y;
            acc[6] += qv * v1.z; acc[7] += qv * v1.w;
        }
        __syncthreads();
    }
    float inv = 1.0f / fmaxf(norm, 1e-6f);
    int l = l0 + lr;
    float* outp = Att + ((long)b * LL + l) * DD + h * 64 + dg * 8;
#pragma unroll
    for (int j = 0; j < 8; j++) outp[j] = acc[j] * inv;
}

// ---------------- pooling ---------------------------------------------
__global__ void score_kernel(const float* __restrict__ Tt, const float* __restrict__ w2,
                             float* __restrict__ S)
{
    int row = blockIdx.x * 8 + (threadIdx.x >> 5);
    int lane = threadIdx.x & 31;
    const float* t = Tt + (long)row * HID;
    float s = 0.f;
    for (int i = lane; i < HID; i += 32) s += t[i] * w2[i];
#pragma unroll
    for (int o = 16; o > 0; o >>= 1) s += __shfl_xor_sync(0xffffffffu, s, o);
    if (lane == 0) S[row] = s;
}

__global__ void softmax_kernel(const float* __restrict__ S, float* __restrict__ Alpha) {
    int b = blockIdx.x, tid = threadIdx.x;  // 256 threads
    __shared__ float sh[8];
    float mx = -1e30f;
    for (int i = tid; i < LL; i += 256) mx = fmaxf(mx, S[b * LL + i]);
#pragma unroll
    for (int o = 16; o > 0; o >>= 1) mx = fmaxf(mx, __shfl_xor_sync(0xffffffffu, mx, o));
    if ((tid & 31) == 0) sh[tid >> 5] = mx;
    __syncthreads();
    if (tid == 0) { float t = sh[0]; for (int i = 1; i < 8; i++) t = fmaxf(t, sh[i]); sh[0] = t; }
    __syncthreads();
    float m = sh[0];
    __syncthreads();
    float sum = 0.f;
    for (int i = tid; i < LL; i += 256) sum += expf(S[b * LL + i] - m);
#pragma unroll
    for (int o = 16; o > 0; o >>= 1) sum += __shfl_xor_sync(0xffffffffu, sum, o);
    if ((tid & 31) == 0) sh[tid >> 5] = sum;
    __syncthreads();
    if (tid == 0) { float t = 0; for (int i = 0; i < 8; i++) t += sh[i]; sh[0] = t; }
    __syncthreads();
    float inv = 1.0f / sh[0];
    for (int i = tid; i < LL; i += 256) Alpha[b * LL + i] = expf(S[b * LL + i] - m) * inv;
}

// ---------------- attentive stats pooling: 2-stage -----------------------
__global__ void muvar_part_kernel(const float* __restrict__ Hx, const float* __restrict__ Alpha,
                                  float* __restrict__ Part)
{
    int b = blockIdx.x, c = blockIdx.y, d = threadIdx.x;  // 512 threads
    float mu = 0.f, sq = 0.f;
    int l0 = c * (LL / 8);
    for (int l = l0; l < l0 + LL / 8; l++) {
        float a = Alpha[b * LL + l];
        float v = Hx[((long)b * LL + l) * DD + d];
        mu += a * v;
        sq += a * v * v;
    }
    Part[((long)(b * 8 + c) * 2) * DD + d]     = mu;
    Part[((long)(b * 8 + c) * 2 + 1) * DD + d] = sq;
}

__global__ void muvar_fin_kernel(const float* __restrict__ Part, float* __restrict__ Feat)
{
    int b = blockIdx.x, d = threadIdx.x;  // 512 threads
    float mu = 0.f, sq = 0.f;
#pragma unroll
    for (int c = 0; c < 8; c++) {
        mu += Part[((long)(b * 8 + c) * 2) * DD + d];
        sq += Part[((long)(b * 8 + c) * 2 + 1) * DD + d];
    }
    Feat[b * 2 * DD + d] = mu;
    Feat[b * 2 * DD + DD + d] = sqrtf(fmaxf(sq - mu * mu, 1e-8f));
}

__global__ void head_kernel(const float* __restrict__ Feat, const float* __restrict__ Wh,
                            const float* __restrict__ bh_, float* __restrict__ Out)
{
    int b = blockIdx.x, tid = threadIdx.x;  // 256 threads
    float p[NC];
#pragma unroll
    for (int n = 0; n < NC; n++) p[n] = 0.f;
    for (int i = tid; i < 2 * DD; i += 256) {
        float f = Feat[b * 2 * DD + i];
        const float* w = Wh + (long)i * NC;
#pragma unroll
        for (int n = 0; n < NC; n++) p[n] += f * w[n];
    }
    __shared__ float red[NC][256];
#pragma unroll
    for (int n = 0; n < NC; n++) red[n][tid] = p[n];
    __syncthreads();
    for (int s = 128; s > 0; s >>= 1) {
        if (tid < s)
#pragma unroll
            for (int n = 0; n < NC; n++) red[n][tid] += red[n][tid + s];
        __syncthreads();
    }
    if (tid < NC) Out[b * NC + tid] = red[tid][0] + bh_[tid];
}

// ---------------- launch --------------------------------------------
extern "C" void kernel_launch(void* const* d_in, const int* in_sizes, int n_in,
                              void* d_out, int out_size)
{
    const float* x        = (const float*)d_in[0];
    const float* patch_W  = (const float*)d_in[1];
    const float* patch_b  = (const float*)d_in[2];
    const float* patch_g  = (const float*)d_in[3];
    const float* patch_be = (const float*)d_in[4];
    const float* ln1_g    = (const float*)d_in[5];
    const float* ln1_b    = (const float*)d_in[6];
    const float* qW       = (const float*)d_in[7];
    const float* kW       = (const float*)d_in[8];
    const float* vW       = (const float*)d_in[9];
    const float* oW       = (const float*)d_in[10];
    const float* ob       = (const float*)d_in[11];
    const float* omega    = (const float*)d_in[12];
    const float* ln2_g    = (const float*)d_in[13];
    const float* ln2_b    = (const float*)d_in[14];
    const float* f1W      = (const float*)d_in[15];
    const float* f1b      = (const float*)d_in[16];
    const float* f2W      = (const float*)d_in[17];
    const float* f2b      = (const float*)d_in[18];
    const float* poolW1   = (const float*)d_in[19];
    const float* poolW2   = (const float*)d_in[20];
    const float* headW    = (const float*)d_in[21];
    const float* headb    = (const float*)d_in[22];
    float* out = (float*)d_out;

    cudaFuncSetAttribute(phi2_kernel, cudaFuncAttributeMaxDynamicSharedMemorySize, PHI_SMEM);

    float* arena;
    cudaGetSymbolAddress((void**)&arena, g_arena);
    float* h    = arena + OFF_H;
    float* a    = arena + OFF_A;
    float* big  = arena + OFF_BIG;
    float* q    = big;
    float* k    = big + SZ_H;
    float* v    = big + 2 * SZ_H;
    float* ffn  = big;
    float* qf   = arena + OFF_QF;
    float* kf   = arena + OFF_KF;
    float* tok  = arena + OFF_ATT;
    float* att  = arena + OFF_ATT;
    float* kv   = arena + OFF_KV;
    float* ksum = arena + OFF_KSUM;
    float* scr  = arena + OFF_SCR;
    float* alp  = arena + OFF_ALP;
    float* feat = arena + OFF_FEAT;
    float* part = arena + OFF_PART;

    dim3 g512(DD / 128, ROWS / 128);    // (4, 200)
    dim3 g1024(FFND / 128, ROWS / 128); // (8, 200)
    dim3 g128(HID / 128, ROWS / 128);   // (1, 200)

    // patchify + embed + LN
    patchify_kernel<<<ROWS, CP>>>(x, tok);
    gemm_fp16_kernel<0, false><<<g512, 256>>>(tok, patch_W, patch_b, a, ROWS, DD, CP);
    ln_kernel<<<ROWS, 256>>>(a, patch_g, patch_be, h);

    for (int l = 0; l < NLAYER; l++) {
        // attention
        ln_kernel<<<ROWS, 256>>>(h, ln1_g + l * DD, ln1_b + l * DD, a);
        gemm_fp16_kernel<0, false><<<g512, 256>>>(a, qW + (long)l * DD * DD, nullptr, q, ROWS, DD, DD);
        gemm_fp16_kernel<0, false><<<g512, 256>>>(a, kW + (long)l * DD * DD, nullptr, k, ROWS, DD, DD);
        gemm_fp16_kernel<0, false><<<g512, 256>>>(a, vW + (long)l * DD * DD, nullptr, v, ROWS, DD, DD);
        phi2_kernel<<<dim3(ROWS / 8, 2), 256, PHI_SMEM>>>(q, k, omega + (long)l * DHH * MM, qf, kf);
        ksum_kernel<<<BB * HH, MM>>>(kf, ksum);
        kv_kernel<<<BB * HH * 2, 256>>>(kf, v, kv);
        attn_out_kernel<<<dim3(BB * HH, LL / 32), 256>>>(qf, kv, ksum, att);
        gemm_fp16_kernel<0, true><<<g512, 256>>>(att, oW + (long)l * DD * DD, ob + l * DD, h, ROWS, DD, DD);
        // FFN
        ln_kernel<<<ROWS, 256>>>(h, ln2_g + l * DD, ln2_b + l * DD, a);
        gemm_fp16_kernel<1, false><<<g1024, 256>>>(a, f1W + (long)l * DD * FFND, f1b + l * FFND, ffn, ROWS, FFND, DD);
        gemm_fp16_kernel<0, true><<<g512, 256>>>(ffn, f2W + (long)l * FFND * DD, f2b + l * DD, h, ROWS, DD, FFND);
    }

    // attentive statistics pooling + head
    gemm_fp16_kernel<2, false><<<g128, 256>>>(h, poolW1, nullptr, ffn, ROWS, HID, DD);
    score_kernel<<<ROWS / 8, 256>>>(ffn, poolW2, scr);
    softmax_kernel<<<BB, 256>>>(scr, alp);
    muvar_part_kernel<<<dim3(BB, 8), DD>>>(h, alp, part);
    muvar_fin_kernel<<<BB, DD>>>(part, feat);
    head_kernel<<<BB, 256>>>(feat, headW, headb, out);
}

// round 14
// speedup vs baseline: 2.7141x; 1.1071x over previous
#include <cuda_runtime.h>
#include <cuda_fp16.h>
#include <math.h>
#include <stdint.h>

// ---------------- problem dims ----------------
#define BB   32
#define CC   8
#define TT   20000
#define PP   25
#define LL   800        // TT/PP
#define CP   200        // CC*PP
#define DD   512
#define HH   8
#define DHH  64
#define MM   256
#define NLAYER 2
#define FFND 1024
#define NC   10
#define HID  128
#define ROWS (BB*LL)    // 25600

// ---------------- packed-weight arena offsets (u32 units) ---------------
#define HW_PATCH 0                              // 112 x 512
#define HW_QKVO(l)  (57344 + (l)*524288)        // q,k,v,o each 256x512
#define HW_F1(l)    (1105920 + (l)*262144)      // 256 x 1024
#define HW_F2(l)    (1630208 + (l)*262144)      // 512 x 512
#define HW_POOL     2154496                     // 256 x 128
#define HW_TOTAL    2187264

// ---------------- scratch arena ----------------
#define SZ_H    (ROWS*DD)
#define SZ_BIG  (3*ROWS*DD)
#define SZ_PHI  (BB*HH*LL*MM)
#define OFF_H    0
#define OFF_A    (OFF_H   + SZ_H)
#define OFF_BIG  (OFF_A   + SZ_H)
#define OFF_QF   (OFF_BIG + SZ_BIG)
#define OFF_KF   (OFF_QF  + SZ_PHI)
#define OFF_ATT  (OFF_KF  + SZ_PHI)
#define OFF_KV   (OFF_ATT + SZ_H)
#define OFF_KSUM (OFF_KV  + BB*HH*MM*DHH)
#define OFF_SCR  (OFF_KSUM+ BB*HH*MM)
#define OFF_ALP  (OFF_SCR + ROWS)
#define OFF_FEAT (OFF_ALP + ROWS)
#define OFF_PART (OFF_FEAT + BB*2*DD)
#define OFF_HA   (OFF_PART + BB*8*2*DD)         // ROWS x 512 u32 (max Kp=1024)
#define OFF_HW   (OFF_HA + ROWS*512)
#define ARENA_SZ (OFF_HW + HW_TOTAL)

__device__ float g_arena[ARENA_SZ];

// ---------------- fp16 helpers ----------------
__device__ __forceinline__ uint32_t pack_h2(float e0, float e1) {
    __half2 t = __floats2half2_rn(e0, e1);   // .x = low half = even-k element
    uint32_t r; *(__half2*)&r = t; return r;
}
__device__ __forceinline__ void mma_fp16(float* d, const uint32_t* a, const uint32_t* b) {
    asm volatile(
        "mma.sync.aligned.m16n8k16.row.col.f32.f16.f16.f32 "
        "{%0,%1,%2,%3}, {%4,%5,%6,%7}, {%8,%9}, {%0,%1,%2,%3};"
        : "+f"(d[0]), "+f"(d[1]), "+f"(d[2]), "+f"(d[3])
        : "r"(a[0]), "r"(a[1]), "r"(a[2]), "r"(a[3]), "r"(b[0]), "r"(b[1]));
}

// ---------------- converters ----------------
// W (K x N fp32) -> packed u32 [Kp2][N], elem (p,n) = half2(W[2p][n], W[2p+1][n])
__global__ void convW_kernel(const float* __restrict__ W, uint32_t* __restrict__ Wp,
                             int K, int N) {
    long i = (long)blockIdx.x * 256 + threadIdx.x;   // grid sized exactly Kp2*N/256
    int p = (int)(i / N), n = (int)(i % N);
    float e0 = (2 * p     < K) ? W[(long)(2 * p) * N + n]     : 0.f;
    float e1 = (2 * p + 1 < K) ? W[(long)(2 * p + 1) * N + n] : 0.f;
    Wp[i] = pack_h2(e0, e1);
}

// A (ROWS x K fp32, K even) -> packed u32 [ROWS][Kp2]
__global__ void convA_kernel(const float* __restrict__ A, uint32_t* __restrict__ Ah, int K) {
    long row = blockIdx.x;
    int Kp2 = K >> 1;
    for (int j = threadIdx.x; j < Kp2; j += 256) {
        int k = 2 * j;
        Ah[row * Kp2 + j] = pack_h2(A[row * K + k], A[row * K + k + 1]);
    }
}

// patchify straight into packed fp16 (Kp=224, zero-padded past CP=200)
__global__ void patchify_pack_kernel(const float* __restrict__ x, uint32_t* __restrict__ Ah) {
    int bl = blockIdx.x;
    int b = bl / LL, l = bl % LL;
    int j = threadIdx.x;          // 112 threads
    float e0 = 0.f, e1 = 0.f;
    int k0 = 2 * j;
    if (k0 < CP)     { int c = k0 / PP, p = k0 % PP; e0 = x[(b * CC + c) * TT + l * PP + p]; }
    int k1 = 2 * j + 1;
    if (k1 < CP)     { int c = k1 / PP, p = k1 % PP; e1 = x[(b * CC + c) * TT + l * PP + p]; }
    Ah[(long)bl * 112 + j] = pack_h2(e0, e1);
}

// ---------------- 1-pass fp16 GEMM, pre-packed inputs --------------------
// C = act(A@W + bias) [+C].  A32:[ROWS][Kp/2] u32, W32:[Kp/2][N] u32, C fp32.
// Tiles 128x128x32, 256 thr (8 warps 2m x 4n, warp tile 64x32), double-buffered.
#define AS 20
#define BS 136
#define A_TILE (128 * AS)              // 2560 u32
#define B_TILE (16 * BS)               // 2176 u32
#define SMEM_U32 (2 * A_TILE + 2 * B_TILE)   // 37888 B

template<int ACT, bool RESID>
__global__ void __launch_bounds__(256, 2)
gemm_fp16_kernel(const uint32_t* __restrict__ A32, const uint32_t* __restrict__ W32,
                 const float* __restrict__ bias, float* __restrict__ C,
                 int N, int Kp)
{
    __shared__ uint32_t sm[SMEM_U32];
    uint32_t* AHp = sm;                     // 2 buffers of A_TILE
    uint32_t* BHp = sm + 2 * A_TILE;        // 2 buffers of B_TILE

    int tid = threadIdx.x;
    int lane = tid & 31, wid = tid >> 5;
    int wm = wid & 1, wn = wid >> 1;
    int m0 = blockIdx.y * 128, n0 = blockIdx.x * 128;
    int K2 = Kp >> 1;                       // u32 per A row
    int nK = Kp >> 5;                       // 32-wide k tiles (Kp always multiple of 32)

    float acc[4][4][4];
#pragma unroll
    for (int i = 0; i < 4; i++)
#pragma unroll
        for (int j = 0; j < 4; j++)
#pragma unroll
            for (int r = 0; r < 4; r++) acc[i][j][r] = 0.f;

    uint4 aR[2], bR[2];

    auto load_tiles = [&](int kt) {
        int p0 = kt * 16;                   // pair-row base
#pragma unroll
        for (int r = 0; r < 2; r++) {
            int idx = tid + r * 256;        // 0..511 uint4s
            int row = idx >> 2, quad = idx & 3;
            aR[r] = *(const uint4*)&A32[(long)(m0 + row) * K2 + p0 + quad * 4];
        }
#pragma unroll
        for (int r = 0; r < 2; r++) {
            int idx = tid + r * 256;
            int p = idx >> 5, quad = idx & 31;
            bR[r] = *(const uint4*)&W32[(long)(p0 + p) * N + n0 + quad * 4];
        }
    };
    auto store_tiles = [&](int buf) {
        uint32_t* AH = AHp + buf * A_TILE;
        uint32_t* BH = BHp + buf * B_TILE;
#pragma unroll
        for (int r = 0; r < 2; r++) {
            int idx = tid + r * 256;
            int row = idx >> 2, quad = idx & 3;
            *(uint4*)&AH[row * AS + quad * 4] = aR[r];
        }
#pragma unroll
        for (int r = 0; r < 2; r++) {
            int idx = tid + r * 256;
            int p = idx >> 5, quad = idx & 31;
            *(uint4*)&BH[p * BS + quad * 4] = bR[r];
        }
    };

    load_tiles(0);
    store_tiles(0);
    __syncthreads();

    for (int kt = 0; kt < nK; kt++) {
        int buf = kt & 1;
        if (kt + 1 < nK) load_tiles(kt + 1);

        const uint32_t* AH = AHp + buf * A_TILE;
        const uint32_t* BH = BHp + buf * B_TILE;

#pragma unroll
        for (int ks = 0; ks < 2; ks++) {
            int pb = ks * 8;
            uint32_t ahi[4][4];
#pragma unroll
            for (int mt = 0; mt < 4; mt++) {
                int mrow = wm * 64 + mt * 16 + (lane >> 2);
                int p = pb + (lane & 3);
                ahi[mt][0] = AH[mrow * AS + p];
                ahi[mt][1] = AH[(mrow + 8) * AS + p];
                ahi[mt][2] = AH[mrow * AS + p + 4];
                ahi[mt][3] = AH[(mrow + 8) * AS + p + 4];
            }
            uint32_t bhi[4][2];
#pragma unroll
            for (int nt = 0; nt < 4; nt++) {
                int ncol = wn * 32 + nt * 8 + (lane >> 2);
                int p = pb + (lane & 3);
                bhi[nt][0] = BH[p * BS + ncol];
                bhi[nt][1] = BH[(p + 4) * BS + ncol];
            }
#pragma unroll
            for (int mt = 0; mt < 4; mt++)
#pragma unroll
                for (int nt = 0; nt < 4; nt++)
                    mma_fp16(acc[mt][nt], ahi[mt], bhi[nt]);
        }

        if (kt + 1 < nK) {
            store_tiles(buf ^ 1);
            __syncthreads();
        }
    }

    // -------- epilogue --------
#pragma unroll
    for (int mt = 0; mt < 4; mt++) {
#pragma unroll
        for (int nt = 0; nt < 4; nt++) {
            int row = m0 + wm * 64 + mt * 16 + (lane >> 2);
            int col = n0 + wn * 32 + nt * 8 + (lane & 3) * 2;
#pragma unroll
            for (int r = 0; r < 4; r++) {
                int rr = row + (r >> 1) * 8;
                int cc = col + (r & 1);
                float v = acc[mt][nt][r];
                if (bias) v += bias[cc];
                if (ACT == 1) v = 0.5f * v * (1.0f + erff(v * 0.70710678118654752f));
                if (ACT == 2) v = tanhf(v);
                float* cp = &C[(long)rr * N + cc];
                if (RESID) v += *cp;
                *cp = v;
            }
        }
    }
}

// ---------------- LayerNorm over D=512 -------------------------------
__global__ void ln_kernel(const float* __restrict__ X, const float* __restrict__ g,
                          const float* __restrict__ bta, float* __restrict__ Y)
{
    long row = blockIdx.x;
    int tid = threadIdx.x;  // 256
    __shared__ float sh[8];
    float v0 = X[row * DD + tid];
    float v1 = X[row * DD + tid + 256];
    float s = v0 + v1;
#pragma unroll
    for (int o = 16; o > 0; o >>= 1) s += __shfl_xor_sync(0xffffffffu, s, o);
    if ((tid & 31) == 0) sh[tid >> 5] = s;
    __syncthreads();
    if (tid == 0) { float t = 0; for (int i = 0; i < 8; i++) t += sh[i]; sh[0] = t; }
    __syncthreads();
    float mu = sh[0] * (1.0f / DD);
    __syncthreads();
    float d0 = v0 - mu, d1 = v1 - mu;
    s = d0 * d0 + d1 * d1;
#pragma unroll
    for (int o = 16; o > 0; o >>= 1) s += __shfl_xor_sync(0xffffffffu, s, o);
    if ((tid & 31) == 0) sh[tid >> 5] = s;
    __syncthreads();
    if (tid == 0) { float t = 0; for (int i = 0; i < 8; i++) t += sh[i]; sh[0] = t; }
    __syncthreads();
    float var = sh[0] * (1.0f / DD);
    float rstd = rsqrtf(var + 1e-5f);
    Y[row * DD + tid]       = d0 * rstd * g[tid]       + bta[tid];
    Y[row * DD + tid + 256] = d1 * rstd * g[tid + 256] + bta[tid + 256];
}

// ---------------- FAVOR+ phi, smem-staged: 8 tokens/block -----------------
#define PHI_SMEM ((16384 + 4096) * 4)   // omega 64KB + xs 16KB
__global__ void __launch_bounds__(256)
phi2_kernel(const float* __restrict__ Q, const float* __restrict__ K,
            const float* __restrict__ omega,
            float* __restrict__ QPhi, float* __restrict__ KPhi)
{
    extern __shared__ float ps[];
    float* om_s = ps;            // [64][256]
    float* xs_s = ps + 16384;    // [8][512]
    const float* X = blockIdx.y ? K : Q;
    float* Phi = blockIdx.y ? KPhi : QPhi;
    int bl0 = blockIdx.x * 8;
    int tid = threadIdx.x, lane = tid & 31, h = tid >> 5;
    const float inv4 = 0.35355339059327379f;  // 1/64^0.25

#pragma unroll
    for (int i = 0; i < 16; i++) {
        int idx = tid * 4 + i * 1024;
        *(float4*)&om_s[idx] = *(const float4*)&omega[idx];
    }
#pragma unroll
    for (int i = 0; i < 4; i++) {
        int idx = tid * 4 + i * 1024;
        float4 v = *(const float4*)&X[(long)bl0 * DD + idx];
        v.x *= inv4; v.y *= inv4; v.z *= inv4; v.w *= inv4;
        *(float4*)&xs_s[idx] = v;
    }
    __syncthreads();

    float acc[8][8], nsq[8];
#pragma unroll
    for (int t = 0; t < 8; t++) {
        nsq[t] = 0.f;
#pragma unroll
        for (int j = 0; j < 8; j++) acc[t][j] = 0.f;
    }
    for (int d = 0; d < DHH; d++) {
        float om8[8];
#pragma unroll
        for (int j = 0; j < 8; j++) om8[j] = om_s[d * MM + lane + 32 * j];
#pragma unroll
        for (int t = 0; t < 8; t++) {
            float xv = xs_s[t * DD + h * DHH + d];
            nsq[t] += xv * xv;
#pragma unroll
            for (int j = 0; j < 8; j++) acc[t][j] += xv * om8[j];
        }
    }
    int b = bl0 / LL, l0 = bl0 % LL;
#pragma unroll
    for (int t = 0; t < 8; t++) {
        float ns = 0.5f * nsq[t];
        float* outp = Phi + ((long)(b * HH + h) * LL + l0 + t) * MM + lane;
#pragma unroll
        for (int j = 0; j < 8; j++) outp[j * 32] = expf(acc[t][j] - ns) * 0.0625f;
    }
}

// ---------------- Ksum ----------------------------
__global__ void ksum_kernel(const float* __restrict__ Kf, float* __restrict__ Ksum) {
    int bh = blockIdx.x;
    int m = threadIdx.x;   // 256
    const float* p = Kf + (long)bh * LL * MM + m;
    float s = 0.f;
    for (int l = 0; l < LL; l++) s += p[l * MM];
    Ksum[bh * MM + m] = s;
}

// ---------------- KV[b,h,m,d] = sum_l Kf[l,m] V[l,d] ----------------
__global__ void __launch_bounds__(256)
kv_kernel(const float* __restrict__ Kf, const float* __restrict__ V,
          float* __restrict__ KV)
{
    int bh = blockIdx.x >> 1, mh = blockIdx.x & 1;
    int b = bh / HH, h = bh % HH;
    __shared__ float Ks[32][128];
    __shared__ float Vs[32][64];
    int tid = threadIdx.x;
    int tm = tid >> 3, td = tid & 7;
    float acc[4][8];
#pragma unroll
    for (int i = 0; i < 4; i++)
#pragma unroll
        for (int j = 0; j < 8; j++) acc[i][j] = 0.f;

    for (int l0 = 0; l0 < LL; l0 += 32) {
#pragma unroll
        for (int r = 0; r < 4; r++) {
            int idx = tid * 4 + r * 1024;
            int lr = idx >> 7, mc = idx & 127;
            *(float4*)&Ks[lr][mc] =
                *(const float4*)&Kf[((long)bh * LL + l0 + lr) * MM + mh * 128 + mc];
        }
#pragma unroll
        for (int r = 0; r < 2; r++) {
            int idx = tid * 4 + r * 1024;
            int lr = idx >> 6, dc = idx & 63;
            *(float4*)&Vs[lr][dc] =
                *(const float4*)&V[((long)b * LL + l0 + lr) * DD + h * 64 + dc];
        }
        __syncthreads();
#pragma unroll 4
        for (int l = 0; l < 32; l++) {
            float km[4];
#pragma unroll
            for (int i = 0; i < 4; i++) km[i] = Ks[l][tm * 4 + i];
            float4 v0 = *(float4*)&Vs[l][td * 8];
            float4 v1 = *(float4*)&Vs[l][td * 8 + 4];
            float vr[8] = {v0.x, v0.y, v0.z, v0.w, v1.x, v1.y, v1.z, v1.w};
#pragma unroll
            for (int i = 0; i < 4; i++)
#pragma unroll
                for (int j = 0; j < 8; j++) acc[i][j] += km[i] * vr[j];
        }
        __syncthreads();
    }
#pragma unroll
    for (int i = 0; i < 4; i++) {
        int m = mh * 128 + tm * 4 + i;
#pragma unroll
        for (int j = 0; j < 8; j++)
            KV[((long)bh * MM + m) * DHH + td * 8 + j] = acc[i][j];
    }
}

// ---------------- out = (Qf @ KV) / max(Qf@Ksum,1e-6) ----------------
__global__ void __launch_bounds__(256)
attn_out_kernel(const float* __restrict__ Qf, const float* __restrict__ KV,
                const float* __restrict__ Ksum, float* __restrict__ Att)
{
    int bh = blockIdx.x;
    int l0 = blockIdx.y * 32;
    int b = bh / HH, h = bh % HH;
    __shared__ float Qs[32][64];
    __shared__ float KVs[64][64];
    __shared__ float Ks[64];
    int tid = threadIdx.x;
    int lr = tid >> 3, dg = tid & 7;
    float acc[8];
#pragma unroll
    for (int j = 0; j < 8; j++) acc[j] = 0.f;
    float norm = 0.f;

    for (int mc = 0; mc < 4; mc++) {
        int m0 = mc * 64;
#pragma unroll
        for (int r = 0; r < 2; r++) {
            int idx = tid * 4 + r * 1024;
            int qr = idx >> 6, qm = idx & 63;
            *(float4*)&Qs[qr][qm] =
                *(const float4*)&Qf[((long)bh * LL + l0 + qr) * MM + m0 + qm];
        }
#pragma unroll
        for (int r = 0; r < 4; r++) {
            int idx = tid * 4 + r * 1024;
            int kr = idx >> 6, kd = idx & 63;
            *(float4*)&KVs[kr][kd] =
                *(const float4*)&KV[((long)bh * MM + m0 + kr) * DHH + kd];
        }
        if (tid < 64) Ks[tid] = Ksum[bh * MM + m0 + tid];
        __syncthreads();
#pragma unroll 8
        for (int mm = 0; mm < 64; mm++) {
            float qv = Qs[lr][mm];
            norm += qv * Ks[mm];
            float4 v0 = *(float4*)&KVs[mm][dg * 8];
            float4 v1 = *(float4*)&KVs[mm][dg * 8 + 4];
            acc[0] += qv * v0.x; acc[1] += qv * v0.y;
            acc[2] += qv * v0.z; acc[3] += qv * v0.w;
            acc[4] += qv * v1.x; acc[5] += qv * v1.y;
            acc[6] += qv * v1.z; acc[7] += qv * v1.w;
        }
        __syncthreads();
    }
    float inv = 1.0f / fmaxf(norm, 1e-6f);
    int l = l0 + lr;
    float* outp = Att + ((long)b * LL + l) * DD + h * 64 + dg * 8;
#pragma unroll
    for (int j = 0; j < 8; j++) outp[j] = acc[j] * inv;
}

// ---------------- pooling ---------------------------------------------
__global__ void score_kernel(const float* __restrict__ Tt, const float* __restrict__ w2,
                             float* __restrict__ S)
{
    int row = blockIdx.x * 8 + (threadIdx.x >> 5);
    int lane = threadIdx.x & 31;
    const float* t = Tt + (long)row * HID;
    float s = 0.f;
    for (int i = lane; i < HID; i += 32) s += t[i] * w2[i];
#pragma unroll
    for (int o = 16; o > 0; o >>= 1) s += __shfl_xor_sync(0xffffffffu, s, o);
    if (lane == 0) S[row] = s;
}

__global__ void softmax_kernel(const float* __restrict__ S, float* __restrict__ Alpha) {
    int b = blockIdx.x, tid = threadIdx.x;  // 256 threads
    __shared__ float sh[8];
    float mx = -1e30f;
    for (int i = tid; i < LL; i += 256) mx = fmaxf(mx, S[b * LL + i]);
#pragma unroll
    for (int o = 16; o > 0; o >>= 1) mx = fmaxf(mx, __shfl_xor_sync(0xffffffffu, mx, o));
    if ((tid & 31) == 0) sh[tid >> 5] = mx;
    __syncthreads();
    if (tid == 0) { float t = sh[0]; for (int i = 1; i < 8; i++) t = fmaxf(t, sh[i]); sh[0] = t; }
    __syncthreads();
    float m = sh[0];
    __syncthreads();
    float sum = 0.f;
    for (int i = tid; i < LL; i += 256) sum += expf(S[b * LL + i] - m);
#pragma unroll
    for (int o = 16; o > 0; o >>= 1) sum += __shfl_xor_sync(0xffffffffu, sum, o);
    if ((tid & 31) == 0) sh[tid >> 5] = sum;
    __syncthreads();
    if (tid == 0) { float t = 0; for (int i = 0; i < 8; i++) t += sh[i]; sh[0] = t; }
    __syncthreads();
    float inv = 1.0f / sh[0];
    for (int i = tid; i < LL; i += 256) Alpha[b * LL + i] = expf(S[b * LL + i] - m) * inv;
}

// ---------------- attentive stats pooling: 2-stage -----------------------
__global__ void muvar_part_kernel(const float* __restrict__ Hx, const float* __restrict__ Alpha,
                                  float* __restrict__ Part)
{
    int b = blockIdx.x, c = blockIdx.y, d = threadIdx.x;  // 512 threads
    float mu = 0.f, sq = 0.f;
    int l0 = c * (LL / 8);
    for (int l = l0; l < l0 + LL / 8; l++) {
        float a = Alpha[b * LL + l];
        float v = Hx[((long)b * LL + l) * DD + d];
        mu += a * v;
        sq += a * v * v;
    }
    Part[((long)(b * 8 + c) * 2) * DD + d]     = mu;
    Part[((long)(b * 8 + c) * 2 + 1) * DD + d] = sq;
}

__global__ void muvar_fin_kernel(const float* __restrict__ Part, float* __restrict__ Feat)
{
    int b = blockIdx.x, d = threadIdx.x;  // 512 threads
    float mu = 0.f, sq = 0.f;
#pragma unroll
    for (int c = 0; c < 8; c++) {
        mu += Part[((long)(b * 8 + c) * 2) * DD + d];
        sq += Part[((long)(b * 8 + c) * 2 + 1) * DD + d];
    }
    Feat[b * 2 * DD + d] = mu;
    Feat[b * 2 * DD + DD + d] = sqrtf(fmaxf(sq - mu * mu, 1e-8f));
}

__global__ void head_kernel(const float* __restrict__ Feat, const float* __restrict__ Wh,
                            const float* __restrict__ bh_, float* __restrict__ Out)
{
    int b = blockIdx.x, tid = threadIdx.x;  // 256 threads
    float p[NC];
#pragma unroll
    for (int n = 0; n < NC; n++) p[n] = 0.f;
    for (int i = tid; i < 2 * DD; i += 256) {
        float f = Feat[b * 2 * DD + i];
        const float* w = Wh + (long)i * NC;
#pragma unroll
        for (int n = 0; n < NC; n++) p[n] += f * w[n];
    }
    __shared__ float red[NC][256];
#pragma unroll
    for (int n = 0; n < NC; n++) red[n][tid] = p[n];
    __syncthreads();
    for (int s = 128; s > 0; s >>= 1) {
        if (tid < s)
#pragma unroll
            for (int n = 0; n < NC; n++) red[n][tid] += red[n][tid + s];
        __syncthreads();
    }
    if (tid < NC) Out[b * NC + tid] = red[tid][0] + bh_[tid];
}

// ---------------- launch --------------------------------------------
extern "C" void kernel_launch(void* const* d_in, const int* in_sizes, int n_in,
                              void* d_out, int out_size)
{
    const float* x        = (const float*)d_in[0];
    const float* patch_W  = (const float*)d_in[1];
    const float* patch_b  = (const float*)d_in[2];
    const float* patch_g  = (const float*)d_in[3];
    const float* patch_be = (const float*)d_in[4];
    const float* ln1_g    = (const float*)d_in[5];
    const float* ln1_b    = (const float*)d_in[6];
    const float* qW       = (const float*)d_in[7];
    const float* kW       = (const float*)d_in[8];
    const float* vW       = (const float*)d_in[9];
    const float* oW       = (const float*)d_in[10];
    const float* ob       = (const float*)d_in[11];
    const float* omega    = (const float*)d_in[12];
    const float* ln2_g    = (const float*)d_in[13];
    const float* ln2_b    = (const float*)d_in[14];
    const float* f1W      = (const float*)d_in[15];
    const float* f1b      = (const float*)d_in[16];
    const float* f2W      = (const float*)d_in[17];
    const float* f2b      = (const float*)d_in[18];
    const float* poolW1   = (const float*)d_in[19];
    const float* poolW2   = (const float*)d_in[20];
    const float* headW    = (const float*)d_in[21];
    const float* headb    = (const float*)d_in[22];
    float* out = (float*)d_out;

    cudaFuncSetAttribute(phi2_kernel, cudaFuncAttributeMaxDynamicSharedMemorySize, PHI_SMEM);

    float* arena;
    cudaGetSymbolAddress((void**)&arena, g_arena);
    float* h    = arena + OFF_H;
    float* a    = arena + OFF_A;
    float* big  = arena + OFF_BIG;
    float* q    = big;
    float* k    = big + SZ_H;
    float* v    = big + 2 * SZ_H;
    float* ffn  = big;
    float* qf   = arena + OFF_QF;
    float* kf   = arena + OFF_KF;
    float* att  = arena + OFF_ATT;
    float* kv   = arena + OFF_KV;
    float* ksum = arena + OFF_KSUM;
    float* scr  = arena + OFF_SCR;
    float* alp  = arena + OFF_ALP;
    float* feat = arena + OFF_FEAT;
    float* part = arena + OFF_PART;
    uint32_t* HA = (uint32_t*)(arena + OFF_HA);
    uint32_t* HW = (uint32_t*)(arena + OFF_HW);

    dim3 g512(DD / 128, ROWS / 128);    // (4, 200)
    dim3 g1024(FFND / 128, ROWS / 128); // (8, 200)
    dim3 g128(HID / 128, ROWS / 128);   // (1, 200)

    // ---- pre-pack weights (fp32 -> half2-packed u32) ----
    convW_kernel<<<224, 256>>>(patch_W, HW + HW_PATCH, CP, DD);
    for (int l = 0; l < NLAYER; l++) {
        convW_kernel<<<512, 256>>>(qW + (long)l * DD * DD, HW + HW_QKVO(l),          DD, DD);
        convW_kernel<<<512, 256>>>(kW + (long)l * DD * DD, HW + HW_QKVO(l) + 131072, DD, DD);
        convW_kernel<<<512, 256>>>(vW + (long)l * DD * DD, HW + HW_QKVO(l) + 262144, DD, DD);
        convW_kernel<<<512, 256>>>(oW + (long)l * DD * DD, HW + HW_QKVO(l) + 393216, DD, DD);
        convW_kernel<<<1024, 256>>>(f1W + (long)l * DD * FFND, HW + HW_F1(l), DD, FFND);
        convW_kernel<<<1024, 256>>>(f2W + (long)l * FFND * DD, HW + HW_F2(l), FFND, DD);
    }
    convW_kernel<<<128, 256>>>(poolW1, HW + HW_POOL, DD, HID);

    // ---- patchify + embed + LN ----
    patchify_pack_kernel<<<ROWS, 112>>>(x, HA);
    gemm_fp16_kernel<0, false><<<g512, 256>>>(HA, HW + HW_PATCH, patch_b, a, DD, 224);
    ln_kernel<<<ROWS, 256>>>(a, patch_g, patch_be, h);

    for (int l = 0; l < NLAYER; l++) {
        // attention
        ln_kernel<<<ROWS, 256>>>(h, ln1_g + l * DD, ln1_b + l * DD, a);
        convA_kernel<<<ROWS, 256>>>(a, HA, DD);
        gemm_fp16_kernel<0, false><<<g512, 256>>>(HA, HW + HW_QKVO(l),          nullptr, q, DD, DD);
        gemm_fp16_kernel<0, false><<<g512, 256>>>(HA, HW + HW_QKVO(l) + 131072, nullptr, k, DD, DD);
        gemm_fp16_kernel<0, false><<<g512, 256>>>(HA, HW + HW_QKVO(l) + 262144, nullptr, v, DD, DD);
        phi2_kernel<<<dim3(ROWS / 8, 2), 256, PHI_SMEM>>>(q, k, omega + (long)l * DHH * MM, qf, kf);
        ksum_kernel<<<BB * HH, MM>>>(kf, ksum);
        kv_kernel<<<BB * HH * 2, 256>>>(kf, v, kv);
        attn_out_kernel<<<dim3(BB * HH, LL / 32), 256>>>(qf, kv, ksum, att);
        convA_kernel<<<ROWS, 256>>>(att, HA, DD);
        gemm_fp16_kernel<0, true><<<g512, 256>>>(HA, HW + HW_QKVO(l) + 393216, ob + l * DD, h, DD, DD);
        // FFN
        ln_kernel<<<ROWS, 256>>>(h, ln2_g + l * DD, ln2_b + l * DD, a);
        convA_kernel<<<ROWS, 256>>>(a, HA, DD);
        gemm_fp16_kernel<1, false><<<g1024, 256>>>(HA, HW + HW_F1(l), f1b + l * FFND, ffn, FFND, DD);
        convA_kernel<<<ROWS, 256>>>(ffn, HA, FFND);
        gemm_fp16_kernel<0, true><<<g512, 256>>>(HA, HW + HW_F2(l), f2b + l * DD, h, DD, FFND);
    }

    // attentive statistics pooling + head
    convA_kernel<<<ROWS, 256>>>(h, HA, DD);
    gemm_fp16_kernel<2, false><<<g128, 256>>>(HA, HW + HW_POOL, nullptr, ffn, HID, DD);
    score_kernel<<<ROWS / 8, 256>>>(ffn, poolW2, scr);
    softmax_kernel<<<BB, 256>>>(scr, alp);
    muvar_part_kernel<<<dim3(BB, 8), DD>>>(h, alp, part);
    muvar_fin_kernel<<<BB, DD>>>(part, feat);
    head_kernel<<<BB, 256>>>(feat, headW, headb, out);
}

// round 16
// speedup vs baseline: 2.9342x; 1.0811x over previous
#include <cuda_runtime.h>
#include <cuda_fp16.h>
#include <math.h>
#include <stdint.h>

// ---------------- problem dims ----------------
#define BB   32
#define CC   8
#define TT   20000
#define PP   25
#define LL   800        // TT/PP
#define CP   200        // CC*PP
#define DD   512
#define HH   8
#define DHH  64
#define MM   256
#define NLAYER 2
#define FFND 1024
#define NC   10
#define HID  128
#define ROWS (BB*LL)    // 25600

// ---------------- packed-weight arena offsets (u32 units) ---------------
#define HW_PATCH 0                              // 112 x 512
#define HW_QKVO(l)  (57344 + (l)*524288)        // q,k,v,o each 256x512
#define HW_F1(l)    (1105920 + (l)*262144)      // 256 x 1024
#define HW_F2(l)    (1630208 + (l)*262144)      // 512 x 512
#define HW_POOL     2154496                     // 256 x 128
#define HW_TOTAL    2187264

// ---------------- scratch arena ----------------
#define SZ_H    (ROWS*DD)
#define SZ_BIG  (3*ROWS*DD)
#define SZ_PHI  (BB*HH*LL*MM)
#define OFF_H    0
#define OFF_HB   (OFF_H   + SZ_H)              // packed ffn-hidden u32 (ROWS x 512)
#define OFF_BIG  (OFF_HB  + SZ_H)
#define OFF_QF   (OFF_BIG + SZ_BIG)
#define OFF_KF   (OFF_QF  + SZ_PHI)
#define OFF_FFN  (OFF_KF  + SZ_PHI)            // fp32 pool pre-scores (ROWS x HID)
#define OFF_KV   (OFF_FFN + ROWS*HID)
#define OFF_KSUM (OFF_KV  + BB*HH*MM*DHH)
#define OFF_SCR  (OFF_KSUM+ BB*HH*MM)
#define OFF_ALP  (OFF_SCR + ROWS)
#define OFF_FEAT (OFF_ALP + ROWS)
#define OFF_PART (OFF_FEAT + BB*2*DD)
#define OFF_HA   (OFF_PART + BB*8*2*DD)        // packed activations u32 (ROWS x 512 max)
#define OFF_HW   (OFF_HA + ROWS*512)
#define ARENA_SZ (OFF_HW + HW_TOTAL)

__device__ float g_arena[ARENA_SZ];

// ---------------- fp16 helpers ----------------
__device__ __forceinline__ uint32_t pack_h2(float e0, float e1) {
    __half2 t = __floats2half2_rn(e0, e1);
    uint32_t r; *(__half2*)&r = t; return r;
}
__device__ __forceinline__ void mma_fp16(float* d, const uint32_t* a, const uint32_t* b) {
    asm volatile(
        "mma.sync.aligned.m16n8k16.row.col.f32.f16.f16.f32 "
        "{%0,%1,%2,%3}, {%4,%5,%6,%7}, {%8,%9}, {%0,%1,%2,%3};"
        : "+f"(d[0]), "+f"(d[1]), "+f"(d[2]), "+f"(d[3])
        : "r"(a[0]), "r"(a[1]), "r"(a[2]), "r"(a[3]), "r"(b[0]), "r"(b[1]));
}
__device__ __forceinline__ uint32_t smem_u32p(const void* p) {
    uint32_t a;
    asm("{ .reg .u64 t; cvta.to.shared.u64 t, %1; cvt.u32.u64 %0, t; }" : "=r"(a) : "l"(p));
    return a;
}
__device__ __forceinline__ void cp_async16(uint32_t saddr, const void* gptr) {
    asm volatile("cp.async.cg.shared.global [%0], [%1], 16;" :: "r"(saddr), "l"(gptr));
}
__device__ __forceinline__ void cp_commit() { asm volatile("cp.async.commit_group;"); }
template<int N> __device__ __forceinline__ void cp_wait() {
    asm volatile("cp.async.wait_group %0;" :: "n"(N));
}

// ---------------- converters ----------------
__global__ void convW_kernel(const float* __restrict__ W, uint32_t* __restrict__ Wp,
                             int K, int N) {
    long i = (long)blockIdx.x * 256 + threadIdx.x;
    int p = (int)(i / N), n = (int)(i % N);
    float e0 = (2 * p     < K) ? W[(long)(2 * p) * N + n]     : 0.f;
    float e1 = (2 * p + 1 < K) ? W[(long)(2 * p + 1) * N + n] : 0.f;
    Wp[i] = pack_h2(e0, e1);
}
__global__ void convA_kernel(const float* __restrict__ A, uint32_t* __restrict__ Ah, int K) {
    long row = blockIdx.x;
    int Kp2 = K >> 1;
    for (int j = threadIdx.x; j < Kp2; j += 256) {
        int k = 2 * j;
        Ah[row * Kp2 + j] = pack_h2(A[row * K + k], A[row * K + k + 1]);
    }
}
__global__ void patchify_pack_kernel(const float* __restrict__ x, uint32_t* __restrict__ Ah) {
    int bl = blockIdx.x;
    int b = bl / LL, l = bl % LL;
    int j = threadIdx.x;          // 112 threads
    float e0 = 0.f, e1 = 0.f;
    int k0 = 2 * j;
    if (k0 < CP) { int c = k0 / PP, p = k0 % PP; e0 = x[(b * CC + c) * TT + l * PP + p]; }
    int k1 = 2 * j + 1;
    if (k1 < CP) { int c = k1 / PP, p = k1 % PP; e1 = x[(b * CC + c) * TT + l * PP + p]; }
    Ah[(long)bl * 112 + j] = pack_h2(e0, e1);
}

// ---------------- fp16 GEMM, cp.async 4-stage pipeline -------------------
// OUT: 0 = fp32, 1 = fp32 + resid, 2 = packed half2 u32
#define AS 20
#define BS 136
#define A_TILE (128 * AS)              // 2560 u32
#define B_TILE (16 * BS)               // 2176 u32
#define NSTAGE 4
#define STAGE_U32 (A_TILE + B_TILE)    // 4736
#define GEMM_SMEM (NSTAGE * STAGE_U32 * 4)   // 75776 B

template<int ACT, int OUT>
__global__ void __launch_bounds__(256, 2)
gemm_fp16_kernel(const uint32_t* __restrict__ A32, const uint32_t* __restrict__ W32,
                 const float* __restrict__ bias, void* __restrict__ Cv,
                 int N, int Kp)
{
    extern __shared__ uint32_t sm[];
    uint32_t sbase = smem_u32p(sm);

    int tid = threadIdx.x;
    int lane = tid & 31, wid = tid >> 5;
    int wm = wid & 1, wn = wid >> 1;
    int m0 = blockIdx.y * 128, n0 = blockIdx.x * 128;
    int K2 = Kp >> 1;
    int nK = Kp >> 5;

    float acc[4][4][4];
#pragma unroll
    for (int i = 0; i < 4; i++)
#pragma unroll
        for (int j = 0; j < 4; j++)
#pragma unroll
            for (int r = 0; r < 4; r++) acc[i][j][r] = 0.f;

    int a0row = tid >> 2,         a0q = (tid & 3) * 4;
    int a1row = (tid + 256) >> 2, a1q = ((tid + 256) & 3) * 4;
    int b0p = tid >> 5,           b0q = (tid & 31) * 4;
    int b1p = (tid + 256) >> 5,   b1q = ((tid + 256) & 31) * 4;

    auto issue_stage = [&](int kt, int stg) {
        int p0 = kt * 16;
        uint32_t ab = sbase + (stg * STAGE_U32) * 4;
        uint32_t bb = ab + A_TILE * 4;
        cp_async16(ab + (a0row * AS + a0q) * 4, &A32[(long)(m0 + a0row) * K2 + p0 + a0q]);
        cp_async16(ab + (a1row * AS + a1q) * 4, &A32[(long)(m0 + a1row) * K2 + p0 + a1q]);
        cp_async16(bb + (b0p * BS + b0q) * 4,  &W32[(long)(p0 + b0p) * N + n0 + b0q]);
        cp_async16(bb + (b1p * BS + b1q) * 4,  &W32[(long)(p0 + b1p) * N + n0 + b1q]);
        cp_commit();
    };

#pragma unroll
    for (int s = 0; s < NSTAGE - 1; s++) issue_stage(s, s);   // nK >= 7 always

    for (int kt = 0; kt < nK; kt++) {
        cp_wait<NSTAGE - 2>();
        __syncthreads();

        const uint32_t* AH = sm + (kt % NSTAGE) * STAGE_U32;
        const uint32_t* BH = AH + A_TILE;

#pragma unroll
        for (int ks = 0; ks < 2; ks++) {
            int pb = ks * 8;
            uint32_t ahi[4][4];
#pragma unroll
            for (int mt = 0; mt < 4; mt++) {
                int mrow = wm * 64 + mt * 16 + (lane >> 2);
                int p = pb + (lane & 3);
                ahi[mt][0] = AH[mrow * AS + p];
                ahi[mt][1] = AH[(mrow + 8) * AS + p];
                ahi[mt][2] = AH[mrow * AS + p + 4];
                ahi[mt][3] = AH[(mrow + 8) * AS + p + 4];
            }
            uint32_t bhi[4][2];
#pragma unroll
            for (int nt = 0; nt < 4; nt++) {
                int ncol = wn * 32 + nt * 8 + (lane >> 2);
                int p = pb + (lane & 3);
                bhi[nt][0] = BH[p * BS + ncol];
                bhi[nt][1] = BH[(p + 4) * BS + ncol];
            }
#pragma unroll
            for (int mt = 0; mt < 4; mt++)
#pragma unroll
                for (int nt = 0; nt < 4; nt++)
                    mma_fp16(acc[mt][nt], ahi[mt], bhi[nt]);
        }

        if (kt + NSTAGE - 1 < nK) issue_stage(kt + NSTAGE - 1, (kt + NSTAGE - 1) % NSTAGE);
        else cp_commit();          // keep group accounting balanced
        __syncthreads();
    }

    // -------- epilogue --------
#pragma unroll
    for (int mt = 0; mt < 4; mt++) {
#pragma unroll
        for (int nt = 0; nt < 4; nt++) {
            int row = m0 + wm * 64 + mt * 16 + (lane >> 2);
            int col = n0 + wn * 32 + nt * 8 + (lane & 3) * 2;
            float v[4];
#pragma unroll
            for (int r = 0; r < 4; r++) {
                int cc = col + (r & 1);
                float t = acc[mt][nt][r];
                if (bias) t += bias[cc];
                if (ACT == 1) t = 0.5f * t * (1.0f + erff(t * 0.70710678118654752f));
                if (ACT == 2) t = tanhf(t);
                v[r] = t;
            }
            if (OUT == 2) {
                uint32_t* cp = (uint32_t*)Cv;
                int pc = col >> 1, N2 = N >> 1;
                cp[(long)row * N2 + pc]       = pack_h2(v[0], v[1]);
                cp[(long)(row + 8) * N2 + pc] = pack_h2(v[2], v[3]);
            } else {
                float* cp = (float*)Cv;
#pragma unroll
                for (int r = 0; r < 4; r++) {
                    int rr = row + (r >> 1) * 8;
                    int cc = col + (r & 1);
                    float t = v[r];
                    if (OUT == 1) t += cp[(long)rr * N + cc];
                    cp[(long)rr * N + cc] = t;
                }
            }
        }
    }
}

// ---------------- LayerNorm (D=512) -> packed u32 ------------------------
__global__ void ln_pack_kernel(const float* __restrict__ X, const float* __restrict__ g,
                               const float* __restrict__ bta, uint32_t* __restrict__ HA)
{
    long row = blockIdx.x;
    int tid = threadIdx.x;  // 256
    __shared__ float sh[8];
    float2 v = *(const float2*)&X[row * DD + 2 * tid];
    float s = v.x + v.y;
#pragma unroll
    for (int o = 16; o > 0; o >>= 1) s += __shfl_xor_sync(0xffffffffu, s, o);
    if ((tid & 31) == 0) sh[tid >> 5] = s;
    __syncthreads();
    if (tid == 0) { float t = 0; for (int i = 0; i < 8; i++) t += sh[i]; sh[0] = t; }
    __syncthreads();
    float mu = sh[0] * (1.0f / DD);
    __syncthreads();
    float d0 = v.x - mu, d1 = v.y - mu;
    s = d0 * d0 + d1 * d1;
#pragma unroll
    for (int o = 16; o > 0; o >>= 1) s += __shfl_xor_sync(0xffffffffu, s, o);
    if ((tid & 31) == 0) sh[tid >> 5] = s;
    __syncthreads();
    if (tid == 0) { float t = 0; for (int i = 0; i < 8; i++) t += sh[i]; sh[0] = t; }
    __syncthreads();
    float rstd = rsqrtf(sh[0] * (1.0f / DD) + 1e-5f);
    float y0 = d0 * rstd * g[2 * tid]     + bta[2 * tid];
    float y1 = d1 * rstd * g[2 * tid + 1] + bta[2 * tid + 1];
    HA[row * 256 + tid] = pack_h2(y0, y1);
}

// ---------------- fp32 LayerNorm (once, after patch embed) ---------------
__global__ void ln_f32_kernel(const float* __restrict__ X, const float* __restrict__ g,
                              const float* __restrict__ bta, float* __restrict__ Y)
{
    long row = blockIdx.x;
    int tid = threadIdx.x;  // 256
    __shared__ float sh[8];
    float2 v = *(const float2*)&X[row * DD + 2 * tid];
    float s = v.x + v.y;
#pragma unroll
    for (int o = 16; o > 0; o >>= 1) s += __shfl_xor_sync(0xffffffffu, s, o);
    if ((tid & 31) == 0) sh[tid >> 5] = s;
    __syncthreads();
    if (tid == 0) { float t = 0; for (int i = 0; i < 8; i++) t += sh[i]; sh[0] = t; }
    __syncthreads();
    float mu = sh[0] * (1.0f / DD);
    __syncthreads();
    float d0 = v.x - mu, d1 = v.y - mu;
    s = d0 * d0 + d1 * d1;
#pragma unroll
    for (int o = 16; o > 0; o >>= 1) s += __shfl_xor_sync(0xffffffffu, s, o);
    if ((tid & 31) == 0) sh[tid >> 5] = s;
    __syncthreads();
    if (tid == 0) { float t = 0; for (int i = 0; i < 8; i++) t += sh[i]; sh[0] = t; }
    __syncthreads();
    float rstd = rsqrtf(sh[0] * (1.0f / DD) + 1e-5f);
    Y[row * DD + 2 * tid]     = d0 * rstd * g[2 * tid]     + bta[2 * tid];
    Y[row * DD + 2 * tid + 1] = d1 * rstd * g[2 * tid + 1] + bta[2 * tid + 1];
}

// ---------------- FAVOR+ phi, smem-staged: 8 tokens/block ----------------
#define PHI_SMEM ((16384 + 4096) * 4)
__global__ void __launch_bounds__(256)
phi2_kernel(const float* __restrict__ Q, const float* __restrict__ K,
            const float* __restrict__ omega,
            float* __restrict__ QPhi, float* __restrict__ KPhi)
{
    extern __shared__ float ps[];
    float* om_s = ps;
    float* xs_s = ps + 16384;
    const float* X = blockIdx.y ? K : Q;
    float* Phi = blockIdx.y ? KPhi : QPhi;
    int bl0 = blockIdx.x * 8;
    int tid = threadIdx.x, lane = tid & 31, h = tid >> 5;
    const float inv4 = 0.35355339059327379f;

#pragma unroll
    for (int i = 0; i < 16; i++) {
        int idx = tid * 4 + i * 1024;
        *(float4*)&om_s[idx] = *(const float4*)&omega[idx];
    }
#pragma unroll
    for (int i = 0; i < 4; i++) {
        int idx = tid * 4 + i * 1024;
        float4 v = *(const float4*)&X[(long)bl0 * DD + idx];
        v.x *= inv4; v.y *= inv4; v.z *= inv4; v.w *= inv4;
        *(float4*)&xs_s[idx] = v;
    }
    __syncthreads();

    float acc[8][8], nsq[8];
#pragma unroll
    for (int t = 0; t < 8; t++) {
        nsq[t] = 0.f;
#pragma unroll
        for (int j = 0; j < 8; j++) acc[t][j] = 0.f;
    }
    for (int d = 0; d < DHH; d++) {
        float om8[8];
#pragma unroll
        for (int j = 0; j < 8; j++) om8[j] = om_s[d * MM + lane + 32 * j];
#pragma unroll
        for (int t = 0; t < 8; t++) {
            float xv = xs_s[t * DD + h * DHH + d];
            nsq[t] += xv * xv;
#pragma unroll
            for (int j = 0; j < 8; j++) acc[t][j] += xv * om8[j];
        }
    }
    int b = bl0 / LL, l0 = bl0 % LL;
#pragma unroll
    for (int t = 0; t < 8; t++) {
        float ns = 0.5f * nsq[t];
        float* outp = Phi + ((long)(b * HH + h) * LL + l0 + t) * MM + lane;
#pragma unroll
        for (int j = 0; j < 8; j++) outp[j * 32] = expf(acc[t][j] - ns) * 0.0625f;
    }
}

// ---------------- Ksum ----------------------------
__global__ void ksum_kernel(const float* __restrict__ Kf, float* __restrict__ Ksum) {
    int bh = blockIdx.x;
    int m = threadIdx.x;
    const float* p = Kf + (long)bh * LL * MM + m;
    float s = 0.f;
    for (int l = 0; l < LL; l++) s += p[l * MM];
    Ksum[bh * MM + m] = s;
}

// ---------------- KV ----------------
__global__ void __launch_bounds__(256)
kv_kernel(const float* __restrict__ Kf, const float* __restrict__ V,
          float* __restrict__ KV)
{
    int bh = blockIdx.x >> 1, mh = blockIdx.x & 1;
    int b = bh / HH, h = bh % HH;
    __shared__ float Ks[32][128];
    __shared__ float Vs[32][64];
    int tid = threadIdx.x;
    int tm = tid >> 3, td = tid & 7;
    float acc[4][8];
#pragma unroll
    for (int i = 0; i < 4; i++)
#pragma unroll
        for (int j = 0; j < 8; j++) acc[i][j] = 0.f;

    for (int l0 = 0; l0 < LL; l0 += 32) {
#pragma unroll
        for (int r = 0; r < 4; r++) {
            int idx = tid * 4 + r * 1024;
            int lr = idx >> 7, mc = idx & 127;
            *(float4*)&Ks[lr][mc] =
                *(const float4*)&Kf[((long)bh * LL + l0 + lr) * MM + mh * 128 + mc];
        }
#pragma unroll
        for (int r = 0; r < 2; r++) {
            int idx = tid * 4 + r * 1024;
            int lr = idx >> 6, dc = idx & 63;
            *(float4*)&Vs[lr][dc] =
                *(const float4*)&V[((long)b * LL + l0 + lr) * DD + h * 64 + dc];
        }
        __syncthreads();
#pragma unroll 4
        for (int l = 0; l < 32; l++) {
            float km[4];
#pragma unroll
            for (int i = 0; i < 4; i++) km[i] = Ks[l][tm * 4 + i];
            float4 v0 = *(float4*)&Vs[l][td * 8];
            float4 v1 = *(float4*)&Vs[l][td * 8 + 4];
            float vr[8] = {v0.x, v0.y, v0.z, v0.w, v1.x, v1.y, v1.z, v1.w};
#pragma unroll
            for (int i = 0; i < 4; i++)
#pragma unroll
                for (int j = 0; j < 8; j++) acc[i][j] += km[i] * vr[j];
        }
        __syncthreads();
    }
#pragma unroll
    for (int i = 0; i < 4; i++) {
        int m = mh * 128 + tm * 4 + i;
#pragma unroll
        for (int j = 0; j < 8; j++)
            KV[((long)bh * MM + m) * DHH + td * 8 + j] = acc[i][j];
    }
}

// ---------------- attn out -> packed u32 ----------------
__global__ void __launch_bounds__(256)
attn_out_kernel(const float* __restrict__ Qf, const float* __restrict__ KV,
                const float* __restrict__ Ksum, uint32_t* __restrict__ HAout)
{
    int bh = blockIdx.x;
    int l0 = blockIdx.y * 32;
    int b = bh / HH, h = bh % HH;
    __shared__ float Qs[32][64];
    __shared__ float KVs[64][64];
    __shared__ float Ks[64];
    int tid = threadIdx.x;
    int lr = tid >> 3, dg = tid & 7;
    float acc[8];
#pragma unroll
    for (int j = 0; j < 8; j++) acc[j] = 0.f;
    float norm = 0.f;

    for (int mc = 0; mc < 4; mc++) {
        int m0 = mc * 64;
#pragma unroll
        for (int r = 0; r < 2; r++) {
            int idx = tid * 4 + r * 1024;
            int qr = idx >> 6, qm = idx & 63;
            *(float4*)&Qs[qr][qm] =
                *(const float4*)&Qf[((long)bh * LL + l0 + qr) * MM + m0 + qm];
        }
#pragma unroll
        for (int r = 0; r < 4; r++) {
            int idx = tid * 4 + r * 1024;
            int kr = idx >> 6, kd = idx & 63;
            *(float4*)&KVs[kr][kd] =
                *(const float4*)&KV[((long)bh * MM + m0 + kr) * DHH + kd];
        }
        if (tid < 64) Ks[tid] = Ksum[bh * MM + m0 + tid];
        __syncthreads();
#pragma unroll 8
        for (int mm = 0; mm < 64; mm++) {
            float qv = Qs[lr][mm];
            norm += qv * Ks[mm];
            float4 v0 = *(float4*)&KVs[mm][dg * 8];
            float4 v1 = *(float4*)&KVs[mm][dg * 8 + 4];
            acc[0] += qv * v0.x; acc[1] += qv * v0.y;
            acc[2] += qv * v0.z; acc[3] += qv * v0.w;
            acc[4] += qv * v1.x; acc[5] += qv * v1.y;
            acc[6] += qv * v1.z; acc[7] += qv * v1.w;
        }
        __syncthreads();
    }
    float inv = 1.0f / fmaxf(norm, 1e-6f);
    int l = l0 + lr;
    uint32_t* outp = HAout + ((long)(b * LL + l)) * 256 + ((h * 64 + dg * 8) >> 1);
    outp[0] = pack_h2(acc[0] * inv, acc[1] * inv);
    outp[1] = pack_h2(acc[2] * inv, acc[3] * inv);
    outp[2] = pack_h2(acc[4] * inv, acc[5] * inv);
    outp[3] = pack_h2(acc[6] * inv, acc[7] * inv);
}

// ---------------- pooling ---------------------------------------------
__global__ void score_kernel(const float* __restrict__ Tt, const float* __restrict__ w2,
                             float* __restrict__ S)
{
    int row = blockIdx.x * 8 + (threadIdx.x >> 5);
    int lane = threadIdx.x & 31;
    const float* t = Tt + (long)row * HID;
    float s = 0.f;
    for (int i = lane; i < HID; i += 32) s += t[i] * w2[i];
#pragma unroll
    for (int o = 16; o > 0; o >>= 1) s += __shfl_xor_sync(0xffffffffu, s, o);
    if (lane == 0) S[row] = s;
}

__global__ void softmax_kernel(const float* __restrict__ S, float* __restrict__ Alpha) {
    int b = blockIdx.x, tid = threadIdx.x;
    __shared__ float sh[8];
    float mx = -1e30f;
    for (int i = tid; i < LL; i += 256) mx = fmaxf(mx, S[b * LL + i]);
#pragma unroll
    for (int o = 16; o > 0; o >>= 1) mx = fmaxf(mx, __shfl_xor_sync(0xffffffffu, mx, o));
    if ((tid & 31) == 0) sh[tid >> 5] = mx;
    __syncthreads();
    if (tid == 0) { float t = sh[0]; for (int i = 1; i < 8; i++) t = fmaxf(t, sh[i]); sh[0] = t; }
    __syncthreads();
    float m = sh[0];
    __syncthreads();
    float sum = 0.f;
    for (int i = tid; i < LL; i += 256) sum += expf(S[b * LL + i] - m);
#pragma unroll
    for (int o = 16; o > 0; o >>= 1) sum += __shfl_xor_sync(0xffffffffu, sum, o);
    if ((tid & 31) == 0) sh[tid >> 5] = sum;
    __syncthreads();
    if (tid == 0) { float t = 0; for (int i = 0; i < 8; i++) t += sh[i]; sh[0] = t; }
    __syncthreads();
    float inv = 1.0f / sh[0];
    for (int i = tid; i < LL; i += 256) Alpha[b * LL + i] = expf(S[b * LL + i] - m) * inv;
}

__global__ void muvar_part_kernel(const float* __restrict__ Hx, const float* __restrict__ Alpha,
                                  float* __restrict__ Part)
{
    int b = blockIdx.x, c = blockIdx.y, d = threadIdx.x;
    float mu = 0.f, sq = 0.f;
    int l0 = c * (LL / 8);
    for (int l = l0; l < l0 + LL / 8; l++) {
        float a = Alpha[b * LL + l];
        float v = Hx[((long)b * LL + l) * DD + d];
        mu += a * v;
        sq += a * v * v;
    }
    Part[((long)(b * 8 + c) * 2) * DD + d]     = mu;
    Part[((long)(b * 8 + c) * 2 + 1) * DD + d] = sq;
}

__global__ void muvar_fin_kernel(const float* __restrict__ Part, float* __restrict__ Feat)
{
    int b = blockIdx.x, d = threadIdx.x;
    float mu = 0.f, sq = 0.f;
#pragma unroll
    for (int c = 0; c < 8; c++) {
        mu += Part[((long)(b * 8 + c) * 2) * DD + d];
        sq += Part[((long)(b * 8 + c) * 2 + 1) * DD + d];
    }
    Feat[b * 2 * DD + d] = mu;
    Feat[b * 2 * DD + DD + d] = sqrtf(fmaxf(sq - mu * mu, 1e-8f));
}

__global__ void head_kernel(const float* __restrict__ Feat, const float* __restrict__ Wh,
                            const float* __restrict__ bh_, float* __restrict__ Out)
{
    int b = blockIdx.x, tid = threadIdx.x;
    float p[NC];
#pragma unroll
    for (int n = 0; n < NC; n++) p[n] = 0.f;
    for (int i = tid; i < 2 * DD; i += 256) {
        float f = Feat[b * 2 * DD + i];
        const float* w = Wh + (long)i * NC;
#pragma unroll
        for (int n = 0; n < NC; n++) p[n] += f * w[n];
    }
    __shared__ float red[NC][256];
#pragma unroll
    for (int n = 0; n < NC; n++) red[n][tid] = p[n];
    __syncthreads();
    for (int s = 128; s > 0; s >>= 1) {
        if (tid < s)
#pragma unroll
            for (int n = 0; n < NC; n++) red[n][tid] += red[n][tid + s];
        __syncthreads();
    }
    if (tid < NC) Out[b * NC + tid] = red[tid][0] + bh_[tid];
}

// ---------------- launch --------------------------------------------
extern "C" void kernel_launch(void* const* d_in, const int* in_sizes, int n_in,
                              void* d_out, int out_size)
{
    const float* x        = (const float*)d_in[0];
    const float* patch_W  = (const float*)d_in[1];
    const float* patch_b  = (const float*)d_in[2];
    const float* patch_g  = (const float*)d_in[3];
    const float* patch_be = (const float*)d_in[4];
    const float* ln1_g    = (const float*)d_in[5];
    const float* ln1_b    = (const float*)d_in[6];
    const float* qW       = (const float*)d_in[7];
    const float* kW       = (const float*)d_in[8];
    const float* vW       = (const float*)d_in[9];
    const float* oW       = (const float*)d_in[10];
    const float* ob       = (const float*)d_in[11];
    const float* omega    = (const float*)d_in[12];
    const float* ln2_g    = (const float*)d_in[13];
    const float* ln2_b    = (const float*)d_in[14];
    const float* f1W      = (const float*)d_in[15];
    const float* f1b      = (const float*)d_in[16];
    const float* f2W      = (const float*)d_in[17];
    const float* f2b      = (const float*)d_in[18];
    const float* poolW1   = (const float*)d_in[19];
    const float* poolW2   = (const float*)d_in[20];
    const float* headW    = (const float*)d_in[21];
    const float* headb    = (const float*)d_in[22];
    float* out = (float*)d_out;

    cudaFuncSetAttribute(phi2_kernel, cudaFuncAttributeMaxDynamicSharedMemorySize, PHI_SMEM);
    cudaFuncSetAttribute(gemm_fp16_kernel<0, 0>, cudaFuncAttributeMaxDynamicSharedMemorySize, GEMM_SMEM);
    cudaFuncSetAttribute(gemm_fp16_kernel<0, 1>, cudaFuncAttributeMaxDynamicSharedMemorySize, GEMM_SMEM);
    cudaFuncSetAttribute(gemm_fp16_kernel<1, 2>, cudaFuncAttributeMaxDynamicSharedMemorySize, GEMM_SMEM);
    cudaFuncSetAttribute(gemm_fp16_kernel<2, 0>, cudaFuncAttributeMaxDynamicSharedMemorySize, GEMM_SMEM);

    float* arena;
    cudaGetSymbolAddress((void**)&arena, g_arena);
    float* h    = arena + OFF_H;
    float* big  = arena + OFF_BIG;
    float* q    = big;
    float* k    = big + SZ_H;
    float* v    = big + 2 * SZ_H;
    float* qf   = arena + OFF_QF;
    float* kf   = arena + OFF_KF;
    float* ffn  = arena + OFF_FFN;
    float* kv   = arena + OFF_KV;
    float* ksum = arena + OFF_KSUM;
    float* scr  = arena + OFF_SCR;
    float* alp  = arena + OFF_ALP;
    float* feat = arena + OFF_FEAT;
    float* part = arena + OFF_PART;
    uint32_t* HA = (uint32_t*)(arena + OFF_HA);
    uint32_t* HB = (uint32_t*)(arena + OFF_HB);
    uint32_t* HW = (uint32_t*)(arena + OFF_HW);

    dim3 g512(DD / 128, ROWS / 128);    // (4, 200)
    dim3 g1024(FFND / 128, ROWS / 128); // (8, 200)
    dim3 g128(HID / 128, ROWS / 128);   // (1, 200)

    // ---- pre-pack weights ----
    convW_kernel<<<224, 256>>>(patch_W, HW + HW_PATCH, CP, DD);
    for (int l = 0; l < NLAYER; l++) {
        convW_kernel<<<512, 256>>>(qW + (long)l * DD * DD, HW + HW_QKVO(l),          DD, DD);
        convW_kernel<<<512, 256>>>(kW + (long)l * DD * DD, HW + HW_QKVO(l) + 131072, DD, DD);
        convW_kernel<<<512, 256>>>(vW + (long)l * DD * DD, HW + HW_QKVO(l) + 262144, DD, DD);
        convW_kernel<<<512, 256>>>(oW + (long)l * DD * DD, HW + HW_QKVO(l) + 393216, DD, DD);
        convW_kernel<<<1024, 256>>>(f1W + (long)l * DD * FFND, HW + HW_F1(l), DD, FFND);
        convW_kernel<<<1024, 256>>>(f2W + (long)l * FFND * DD, HW + HW_F2(l), FFND, DD);
    }
    convW_kernel<<<128, 256>>>(poolW1, HW + HW_POOL, DD, HID);

    // ---- patchify + embed + LN ----
    patchify_pack_kernel<<<ROWS, 112>>>(x, HA);
    gemm_fp16_kernel<0, 0><<<g512, 256, GEMM_SMEM>>>(HA, HW + HW_PATCH, patch_b, v, DD, 224);
    ln_f32_kernel<<<ROWS, 256>>>(v, patch_g, patch_be, h);

    for (int l = 0; l < NLAYER; l++) {
        // attention
        ln_pack_kernel<<<ROWS, 256>>>(h, ln1_g + l * DD, ln1_b + l * DD, HA);
        gemm_fp16_kernel<0, 0><<<g512, 256, GEMM_SMEM>>>(HA, HW + HW_QKVO(l),          nullptr, q, DD, DD);
        gemm_fp16_kernel<0, 0><<<g512, 256, GEMM_SMEM>>>(HA, HW + HW_QKVO(l) + 131072, nullptr, k, DD, DD);
        gemm_fp16_kernel<0, 0><<<g512, 256, GEMM_SMEM>>>(HA, HW + HW_QKVO(l) + 262144, nullptr, v, DD, DD);
        phi2_kernel<<<dim3(ROWS / 8, 2), 256, PHI_SMEM>>>(q, k, omega + (long)l * DHH * MM, qf, kf);
        ksum_kernel<<<BB * HH, MM>>>(kf, ksum);
        kv_kernel<<<BB * HH * 2, 256>>>(kf, v, kv);
        attn_out_kernel<<<dim3(BB * HH, LL / 32), 256>>>(qf, kv, ksum, HA);
        gemm_fp16_kernel<0, 1><<<g512, 256, GEMM_SMEM>>>(HA, HW + HW_QKVO(l) + 393216, ob + l * DD, h, DD, DD);
        // FFN
        ln_pack_kernel<<<ROWS, 256>>>(h, ln2_g + l * DD, ln2_b + l * DD, HA);
        gemm_fp16_kernel<1, 2><<<g1024, 256, GEMM_SMEM>>>(HA, HW + HW_F1(l), f1b + l * FFND, HB, FFND, DD);
        gemm_fp16_kernel<0, 1><<<g512, 256, GEMM_SMEM>>>(HB, HW + HW_F2(l), f2b + l * DD, h, DD, FFND);
    }

    // attentive statistics pooling + head
    convA_kernel<<<ROWS, 256>>>(h, HA, DD);
    gemm_fp16_kernel<2, 0><<<g128, 256, GEMM_SMEM>>>(HA, HW + HW_POOL, nullptr, ffn, HID, DD);
    score_kernel<<<ROWS / 8, 256>>>(ffn, poolW2, scr);
    softmax_kernel<<<BB, 256>>>(scr, alp);
    muvar_part_kernel<<<dim3(BB, 8), DD>>>(h, alp, part);
    muvar_fin_kernel<<<BB, DD>>>(part, feat);
    head_kernel<<<BB, 256>>>(feat, headW, headb, out);
}